// round 2
// baseline (speedup 1.0000x reference)
#include <cuda_runtime.h>
#include <math.h>

#define BB 8
#define TT 2048
#define DIMX 512
#define DMX 128
#define DINNERX 256
#define NSTATEX 16
#define HDIMX 64
#define NHX 4
#define CONVD 288
#define PROJD 548
#define LNUM 2
#define BT (BB*TT)          // 16384
#define QC 128              // chunk length
#define NCHK (TT/QC)        // 16
#define BHX (BB*NHX)        // 32
#define EPSF 1e-5f

// ------------------------- scratch (static device memory) -------------------
__device__ float g_H[BT*DMX];          // residual stream
__device__ float g_HN[BT*DMX];         // rmsnorm(h)
__device__ float g_PROJ[BT*PROJD];     // in-projection
__device__ float g_CONVX[BT*CONVD];    // silu(conv(hBC))
__device__ float g_DT[BHX*TT];         // softplus(dt+bias), [bh][t]
__device__ float g_CUM[BHX*TT];        // within-chunk inclusive cumsum of dt*A
__device__ float g_SLOC[BHX*NCHK*HDIMX*NSTATEX];  // per-chunk local state
__device__ float g_SIN[BHX*NCHK*HDIMX*NSTATEX];   // state entering each chunk
__device__ float g_Y[BT*DINNERX];
__device__ float g_YN[BT*DINNERX];
__device__ float g_POOL[BB*DMX];

// ------------------------------- GEMM ---------------------------------------
// C[M,N] = A[M,K] @ W[K,N] (+bias) (+=C). BM=128 BN=64 BK=16, 256 threads.
template<bool ADD, bool BIAS>
__global__ __launch_bounds__(256) void gemm_kernel(
    const float* __restrict__ A, const float* __restrict__ W,
    const float* __restrict__ bias, float* __restrict__ C,
    int M, int N, int K)
{
    const int BM = 128, BN = 64, BK = 16;
    __shared__ float As[BK][BM + 4];
    __shared__ float Bs[BK][BN + 4];
    int bm = blockIdx.y * BM, bn = blockIdx.x * BN;
    int tid = threadIdx.x;
    int tx = tid & 15, ty = tid >> 4;
    float acc[8][4];
#pragma unroll
    for (int i = 0; i < 8; i++)
#pragma unroll
        for (int j = 0; j < 4; j++) acc[i][j] = 0.f;

    int ar = tid >> 1, ac = (tid & 1) * 8;   // A tile: 128 rows x 16 k
    int wr = tid >> 4, wc = (tid & 15) * 4;  // W tile: 16 k x 64 n

    for (int k0 = 0; k0 < K; k0 += BK) {
        const float* Ap = A + (long)(bm + ar) * K + k0 + ac;
        float4 a0 = *(const float4*)Ap;
        float4 a1 = *(const float4*)(Ap + 4);
        As[ac + 0][ar] = a0.x; As[ac + 1][ar] = a0.y;
        As[ac + 2][ar] = a0.z; As[ac + 3][ar] = a0.w;
        As[ac + 4][ar] = a1.x; As[ac + 5][ar] = a1.y;
        As[ac + 6][ar] = a1.z; As[ac + 7][ar] = a1.w;

        int n = bn + wc;
        float4 bv;
        if (n + 3 < N) {
            bv = *(const float4*)(W + (long)(k0 + wr) * N + n);
        } else {
            bv.x = (n + 0 < N) ? W[(long)(k0 + wr) * N + n + 0] : 0.f;
            bv.y = (n + 1 < N) ? W[(long)(k0 + wr) * N + n + 1] : 0.f;
            bv.z = (n + 2 < N) ? W[(long)(k0 + wr) * N + n + 2] : 0.f;
            bv.w = 0.f;
        }
        Bs[wr][wc + 0] = bv.x; Bs[wr][wc + 1] = bv.y;
        Bs[wr][wc + 2] = bv.z; Bs[wr][wc + 3] = bv.w;
        __syncthreads();
#pragma unroll
        for (int k = 0; k < BK; k++) {
            float a[8], bb[4];
            *(float4*)(a)     = *(const float4*)&As[k][ty * 8];
            *(float4*)(a + 4) = *(const float4*)&As[k][ty * 8 + 4];
            *(float4*)(bb)    = *(const float4*)&Bs[k][tx * 4];
#pragma unroll
            for (int i = 0; i < 8; i++)
#pragma unroll
                for (int j = 0; j < 4; j++) acc[i][j] += a[i] * bb[j];
        }
        __syncthreads();
    }
#pragma unroll
    for (int i = 0; i < 8; i++) {
        long row = bm + ty * 8 + i;
#pragma unroll
        for (int j = 0; j < 4; j++) {
            int col = bn + tx * 4 + j;
            if (col < N) {
                float v = acc[i][j];
                if (BIAS) v += bias[col];
                long off = row * N + col;
                if (ADD) v += C[off];
                C[off] = v;
            }
        }
    }
}

// ------------------------------ rmsnorm (DM=128) -----------------------------
__global__ void rmsnorm128_kernel(const float* __restrict__ src,
                                  const float* __restrict__ w,
                                  float* __restrict__ dst)
{
    int warp = (blockIdx.x * blockDim.x + threadIdx.x) >> 5;
    int lane = threadIdx.x & 31;
    if (warp >= BT) return;
    const float* row = src + (long)warp * DMX;
    float4 v = *(const float4*)(row + lane * 4);
    float ss = v.x*v.x + v.y*v.y + v.z*v.z + v.w*v.w;
#pragma unroll
    for (int o = 16; o; o >>= 1) ss += __shfl_xor_sync(0xffffffffu, ss, o);
    float r = rsqrtf(ss * (1.f / DMX) + EPSF);
    float4 wv = *(const float4*)(w + lane * 4);
    float4 o;
    o.x = v.x * r * wv.x; o.y = v.y * r * wv.y;
    o.z = v.z * r * wv.z; o.w = v.w * r * wv.w;
    *(float4*)(dst + (long)warp * DMX + lane * 4) = o;
}

// ------------------------ causal depthwise conv + silu -----------------------
__global__ void conv_kernel(const float* __restrict__ cw,
                            const float* __restrict__ cb)
{
    int idx = blockIdx.x * blockDim.x + threadIdx.x;   // over BT*CONVD
    if (idx >= BT * CONVD) return;
    int c  = idx % CONVD;
    int bt = idx / CONVD;
    int t = bt % TT;
    int b = bt / TT;
    float acc = cb[c];
#pragma unroll
    for (int k = 0; k < 4; k++) {
        int tt = t - 3 + k;
        if (tt >= 0)
            acc += cw[c * 4 + k] * g_PROJ[(long)(b * TT + tt) * PROJD + DINNERX + c];
    }
    g_CONVX[idx] = acc / (1.f + __expf(-acc));   // silu
}

// ------------------------------- dt = softplus -------------------------------
__global__ void dt_kernel(const float* __restrict__ dtb)
{
    int idx = blockIdx.x * blockDim.x + threadIdx.x;   // over BT*NH
    if (idx >= BT * NHX) return;
    int h = idx & 3;
    int bt = idx >> 2;
    int t = bt % TT, b = bt / TT;
    float v = g_PROJ[(long)bt * PROJD + DINNERX + CONVD + h] + dtb[h];
    float sp = (v > 20.f) ? v : log1pf(__expf(v));
    g_DT[(b * NHX + h) * TT + t] = sp;
}

// ------------------- within-chunk inclusive cumsum of dt*A -------------------
__global__ void scan_kernel(const float* __restrict__ Alog)
{
    int c = blockIdx.x, bh = blockIdx.y;
    int h = bh & 3;
    int t = threadIdx.x;
    float Ah = -__expf(Alog[h]);
    __shared__ float s[QC];
    int base = bh * TT + c * QC;
    s[t] = g_DT[base + t] * Ah;
    __syncthreads();
#pragma unroll
    for (int off = 1; off < QC; off <<= 1) {
        float v = (t >= off) ? s[t - off] : 0.f;
        __syncthreads();
        s[t] += v;
        __syncthreads();
    }
    g_CUM[base + t] = s[t];
}

// --------------------------- per-chunk local state ---------------------------
// S_local[p,n] = sum_t exp(cum_end - cum_t) * dt_t * x_t[p] * B_t[n]
__global__ __launch_bounds__(256) void chunkstate_kernel()
{
    int c = blockIdx.x, bh = blockIdx.y;
    int b = bh >> 2, h = bh & 3;
    int tid = threadIdx.x;
    __shared__ float coef[QC];
    __shared__ float Xs[16][HDIMX];
    __shared__ float Bsh[16][NSTATEX];
    int cbase = bh * TT + c * QC;
    long rowbase = (long)(b * TT + c * QC);
    if (tid < QC) {
        float ce = g_CUM[cbase + QC - 1];
        coef[tid] = __expf(ce - g_CUM[cbase + tid]) * g_DT[cbase + tid];
    }
    float acc[4] = {0.f, 0.f, 0.f, 0.f};
    int p = tid >> 2, ng = (tid & 3) * 4;
    for (int tt = 0; tt < QC; tt += 16) {
        __syncthreads();
#pragma unroll
        for (int j = 0; j < 4; j++) {
            int li = tid + j * 256;
            int r = li >> 6, pp = li & 63;
            Xs[r][pp] = g_CONVX[(rowbase + tt + r) * CONVD + h * 64 + pp];
        }
        {
            int r = tid >> 4, n = tid & 15;
            Bsh[r][n] = g_CONVX[(rowbase + tt + r) * CONVD + 256 + n];
        }
        __syncthreads();
#pragma unroll
        for (int r = 0; r < 16; r++) {
            float cx = coef[tt + r] * Xs[r][p];
#pragma unroll
            for (int j = 0; j < 4; j++) acc[j] += cx * Bsh[r][ng + j];
        }
    }
    long dst = ((long)bh * NCHK + c) * (HDIMX * NSTATEX) + p * NSTATEX + ng;
    *(float4*)(g_SLOC + dst) = make_float4(acc[0], acc[1], acc[2], acc[3]);
}

// ------------------- chunk-state prefix (16 sequential steps) ----------------
__global__ void prefix_kernel()
{
    int bh = blockIdx.x;
    int i = threadIdx.x * 4;     // 256 threads x 4 elems = 1024
    float4 s = make_float4(0.f, 0.f, 0.f, 0.f);
    long base = (long)bh * NCHK * (HDIMX * NSTATEX);
    for (int c = 0; c < NCHK; c++) {
        *(float4*)(g_SIN + base + c * (HDIMX * NSTATEX) + i) = s;
        float dec = __expf(g_CUM[bh * TT + c * QC + QC - 1]);
        float4 sl = *(const float4*)(g_SLOC + base + c * (HDIMX * NSTATEX) + i);
        s.x = s.x * dec + sl.x; s.y = s.y * dec + sl.y;
        s.z = s.z * dec + sl.z; s.w = s.w * dec + sl.w;
    }
}

// ------------------------------ SSD output -----------------------------------
// y_t[p] = exp(cum_t)*(C_t . S_in)[p] + D*x_t[p]
//        + sum_{s<=t} exp(cum_t-cum_s)*dt_s*(C_t . B_s)*x_s[p]
__global__ __launch_bounds__(128) void ssd_out_kernel(const float* __restrict__ Dp)
{
    int c = blockIdx.x, bh = blockIdx.y;
    int b = bh >> 2, h = bh & 3;
    int t = threadIdx.x;
    __shared__ float sX[QC][HDIMX];          // 32 KB
    __shared__ float sB[QC][NSTATEX];        //  8 KB
    __shared__ float sSin[HDIMX][NSTATEX];   //  4 KB
    __shared__ float sCum[QC];
    __shared__ float sDt[QC];
    long rowbase = (long)(b * TT + c * QC);
    int cbase = bh * TT + c * QC;

    for (int j = 0; j < 64; j++) {
        int li = t + j * 128;
        int r = li >> 6, p = li & 63;
        sX[r][p] = g_CONVX[(rowbase + r) * CONVD + h * 64 + p];
    }
    for (int j = 0; j < 16; j++) {
        int li = t + j * 128;
        int r = li >> 4, n = li & 15;
        sB[r][n] = g_CONVX[(rowbase + r) * CONVD + 256 + n];
    }
    for (int j = 0; j < 8; j++) {
        int li = t + j * 128;
        ((float*)sSin)[li] = g_SIN[((long)bh * NCHK + c) * (HDIMX * NSTATEX) + li];
    }
    sCum[t] = g_CUM[cbase + t];
    sDt[t]  = g_DT[cbase + t];
    float Creg[16];
#pragma unroll
    for (int n = 0; n < 16; n++)
        Creg[n] = g_CONVX[(rowbase + t) * CONVD + 272 + n];
    __syncthreads();

    float ct  = sCum[t];
    float ect = __expf(ct);
    float Dh  = Dp[h];
    float y[64];
#pragma unroll
    for (int p = 0; p < 64; p++) {
        float a = 0.f;
#pragma unroll
        for (int n = 0; n < 16; n++) a += Creg[n] * sSin[p][n];
        y[p] = ect * a + Dh * sX[t][p];
    }

    int smax = t | 31;      // uniform within warp -> early exit for low warps
    for (int s = 0; s <= smax; s++) {
        if (s <= t) {
            float d = 0.f;
#pragma unroll
            for (int n = 0; n < 16; n++) d += Creg[n] * sB[s][n];
            float g = __expf(ct - sCum[s]) * sDt[s] * d;
#pragma unroll
            for (int p = 0; p < 64; p++) y[p] += g * sX[s][p];
        }
    }

    __syncthreads();                 // everyone done reading sX
#pragma unroll
    for (int p = 0; p < 64; p++) sX[t][p] = y[p];
    __syncthreads();
    for (int j = 0; j < 64; j++) {   // coalesced store
        int li = t + j * 128;
        int r = li >> 6, p = li & 63;
        g_Y[(rowbase + r) * DINNERX + h * 64 + p] = sX[r][p];
    }
}

// --------------------------- gated rmsnorm (256) -----------------------------
__global__ void gatednorm_kernel(const float* __restrict__ gnw)
{
    int warp = (blockIdx.x * blockDim.x + threadIdx.x) >> 5;
    int lane = threadIdx.x & 31;
    if (warp >= BT) return;
    const float* yr = g_Y + (long)warp * DINNERX;
    const float* gr = g_PROJ + (long)warp * PROJD;
    float v[8];
    float ss = 0.f;
#pragma unroll
    for (int i = 0; i < 8; i++) {
        int d = lane * 8 + i;
        float g = gr[d];
        float vv = yr[d] * (g / (1.f + __expf(-g)));
        v[i] = vv;
        ss += vv * vv;
    }
#pragma unroll
    for (int o = 16; o; o >>= 1) ss += __shfl_xor_sync(0xffffffffu, ss, o);
    float r = rsqrtf(ss * (1.f / DINNERX) + EPSF);
#pragma unroll
    for (int i = 0; i < 8; i++) {
        int d = lane * 8 + i;
        g_YN[(long)warp * DINNERX + d] = v[i] * r * gnw[d];
    }
}

// ---------------------------- final pool + head ------------------------------
__global__ void zero_pool_kernel()
{
    int i = blockIdx.x * blockDim.x + threadIdx.x;
    if (i < BB * DMX) g_POOL[i] = 0.f;
}

__global__ __launch_bounds__(128) void pool_kernel(const float* __restrict__ nfw)
{
    int b = blockIdx.y;
    int chunk = blockIdx.x;          // 32 chunks of 64 rows
    int d = threadIdx.x;
    __shared__ float wsum[4];
    float wnf = nfw[d];
    float acc = 0.f;
    for (int r = 0; r < 64; r++) {
        int t = chunk * 64 + r;
        float v = g_H[(long)(b * TT + t) * DMX + d];
        float ss = v * v;
#pragma unroll
        for (int o = 16; o; o >>= 1) ss += __shfl_xor_sync(0xffffffffu, ss, o);
        if ((d & 31) == 0) wsum[d >> 5] = ss;
        __syncthreads();
        float tot = wsum[0] + wsum[1] + wsum[2] + wsum[3];
        __syncthreads();
        acc += v * rsqrtf(tot * (1.f / DMX) + EPSF) * wnf;
    }
    atomicAdd(&g_POOL[b * DMX + d], acc * (1.f / TT));
}

__global__ void final_kernel(const float* __restrict__ ow,
                             const float* __restrict__ ob,
                             float* __restrict__ out)
{
    int b = blockIdx.x;
    int j = threadIdx.x;             // 512 threads
    __shared__ float p[DMX];
    if (j < DMX) p[j] = g_POOL[b * DMX + j];
    __syncthreads();
    float acc = ob[j];
#pragma unroll 4
    for (int k = 0; k < DMX; k++) acc += p[k] * ow[k * DIMX + j];
    out[b * DIMX + j] = acc;
}

// ------------------------------ launcher -------------------------------------
extern "C" void kernel_launch(void* const* d_in, const int* in_sizes, int n_in,
                              void* d_out, int out_size)
{
    const float* x         = (const float*)d_in[0];
    const float* in_w      = (const float*)d_in[1];
    const float* in_b      = (const float*)d_in[2];
    const float* norm_w    = (const float*)d_in[3];
    const float* inproj_w  = (const float*)d_in[4];
    const float* conv_w    = (const float*)d_in[5];
    const float* conv_b    = (const float*)d_in[6];
    const float* A_log     = (const float*)d_in[7];
    const float* Dparam    = (const float*)d_in[8];
    const float* dt_bias   = (const float*)d_in[9];
    const float* gnorm_w   = (const float*)d_in[10];
    const float* outproj_w = (const float*)d_in[11];
    const float* normf_w   = (const float*)d_in[12];
    const float* out_w     = (const float*)d_in[13];
    const float* out_b     = (const float*)d_in[14];

    float *pH, *pHN, *pPROJ, *pYN;
    cudaGetSymbolAddress((void**)&pH,    g_H);
    cudaGetSymbolAddress((void**)&pHN,   g_HN);
    cudaGetSymbolAddress((void**)&pPROJ, g_PROJ);
    cudaGetSymbolAddress((void**)&pYN,   g_YN);

    // h = x @ in_w + in_b
    gemm_kernel<false, true><<<dim3(DMX / 64, BT / 128), 256>>>(
        x, in_w, in_b, pH, BT, DMX, DIMX);

    for (int l = 0; l < LNUM; l++) {
        rmsnorm128_kernel<<<BT / 8, 256>>>(pH, norm_w + l * DMX, pHN);
        gemm_kernel<false, false><<<dim3((PROJD + 63) / 64, BT / 128), 256>>>(
            pHN, inproj_w + (long)l * DMX * PROJD, nullptr, pPROJ, BT, PROJD, DMX);
        conv_kernel<<<(BT * CONVD + 255) / 256, 256>>>(
            conv_w + l * CONVD * 4, conv_b + l * CONVD);
        dt_kernel<<<(BT * NHX) / 256, 256>>>(dt_bias + l * NHX);
        scan_kernel<<<dim3(NCHK, BHX), QC>>>(A_log + l * NHX);
        chunkstate_kernel<<<dim3(NCHK, BHX), 256>>>();
        prefix_kernel<<<BHX, 256>>>();
        ssd_out_kernel<<<dim3(NCHK, BHX), QC>>>(Dparam + l * NHX);
        gatednorm_kernel<<<BT / 8, 256>>>(gnorm_w + l * DINNERX);
        gemm_kernel<true, false><<<dim3(DMX / 64, BT / 128), 256>>>(
            pYN, outproj_w + (long)l * DINNERX * DMX, nullptr, pH, BT, DMX, DINNERX);
    }

    zero_pool_kernel<<<4, 256>>>();
    pool_kernel<<<dim3(32, BB), DMX>>>(normf_w);
    final_kernel<<<BB, DIMX>>>(out_w, out_b, (float*)d_out);
}

// round 4
// speedup vs baseline: 1.1671x; 1.1671x over previous
#include <cuda_runtime.h>
#include <cuda_bf16.h>
#include <math.h>
#include <stdint.h>

#define BB 8
#define TT 2048
#define DIMX 512
#define DMX 128
#define DINNERX 256
#define NSTATEX 16
#define HDIMX 64
#define NHX 4
#define CONVD 288
#define PROJD 548
#define PROJPAD 576
#define LNUM 2
#define BT (BB*TT)          // 16384
#define QC 128              // chunk length
#define NCHK (TT/QC)        // 16
#define BHX (BB*NHX)        // 32
#define EPSF 1e-5f

// ------------------------- scratch (static device memory) -------------------
__device__ float g_H[BT*DMX];          // residual stream
__device__ float g_PROJ[BT*PROJD];     // in-projection
__device__ float g_CONVX[BT*CONVD];    // silu(conv(hBC))
__device__ float g_DT[BHX*TT];         // softplus(dt+bias), [bh][t]
__device__ float g_CUM[BHX*TT];        // within-chunk inclusive cumsum of dt*A
__device__ float g_SLOC[BHX*NCHK*HDIMX*NSTATEX];  // per-chunk local state
__device__ float g_SIN[BHX*NCHK*HDIMX*NSTATEX];   // state entering each chunk
__device__ float g_Y[BT*DINNERX];
__device__ float g_POOL[BB*DMX];

// bf16 split activations / weights
__device__ __nv_bfloat16 g_xhi[BT*DIMX],    g_xlo[BT*DIMX];
__device__ __nv_bfloat16 g_hnhi[BT*DMX],    g_hnlo[BT*DMX];
__device__ __nv_bfloat16 g_ynhi[BT*DINNERX],g_ynlo[BT*DINNERX];
__device__ __nv_bfloat16 g_w1hi[DMX*DIMX],  g_w1lo[DMX*DIMX];             // in_w^T [128][512]
__device__ __nv_bfloat16 g_w2hi[LNUM*PROJPAD*DMX], g_w2lo[LNUM*PROJPAD*DMX]; // inproj^T [576][128]
__device__ __nv_bfloat16 g_w3hi[LNUM*DMX*DINNERX], g_w3lo[LNUM*DMX*DINNERX]; // outproj^T [128][256]

// ------------------------------ PTX helpers ---------------------------------
__device__ __forceinline__ uint32_t smem_u32(const void* p) {
    uint32_t a;
    asm("{ .reg .u64 t; cvta.to.shared.u64 t, %1; cvt.u32.u64 %0, t; }" : "=r"(a) : "l"(p));
    return a;
}
__device__ __forceinline__ void ldsm_x4(uint32_t* r, uint32_t addr) {
    asm volatile("ldmatrix.sync.aligned.m8n8.x4.shared.b16 {%0,%1,%2,%3}, [%4];"
        : "=r"(r[0]), "=r"(r[1]), "=r"(r[2]), "=r"(r[3]) : "r"(addr));
}
__device__ __forceinline__ void ldsm_x2(uint32_t* r, uint32_t addr) {
    asm volatile("ldmatrix.sync.aligned.m8n8.x2.shared.b16 {%0,%1}, [%2];"
        : "=r"(r[0]), "=r"(r[1]) : "r"(addr));
}
__device__ __forceinline__ void mma16816(float* c, const uint32_t* a, const uint32_t* b) {
    asm volatile("mma.sync.aligned.m16n8k16.row.col.f32.bf16.bf16.f32 "
        "{%0,%1,%2,%3}, {%4,%5,%6,%7}, {%8,%9}, {%0,%1,%2,%3};"
        : "+f"(c[0]), "+f"(c[1]), "+f"(c[2]), "+f"(c[3])
        : "r"(a[0]), "r"(a[1]), "r"(a[2]), "r"(a[3]), "r"(b[0]), "r"(b[1]));
}

// ------------------------------ HMMA GEMM ------------------------------------
// C[M,N] = A[M,K] @ W[K,N], A as bf16 hi/lo [M][K], W as Wt hi/lo [Npad][K]
// (Wt[n][k] = W[k][n]).  Block tile M128 x N64, K staged 64.  3-term bf16 split.
// 8 warps, each 32x32.  MODE 0: C = D + bias ; 1: C = D ; 2: C += D.
#define LDSA 72                       // bf16 row stride (64 + 8 pad)
#define SM_AHI 0
#define SM_ALO (128*LDSA*2)           // 18432
#define SM_BHI (2*128*LDSA*2)         // 36864
#define SM_BLO (SM_BHI + 64*LDSA*2)   // 46080
#define SM_TOTAL (SM_BLO + 64*LDSA*2) // 55296

template<int MODE>
__global__ __launch_bounds__(256) void mma_gemm(
    const __nv_bfloat16* __restrict__ Ahi, const __nv_bfloat16* __restrict__ Alo,
    const __nv_bfloat16* __restrict__ Whi, const __nv_bfloat16* __restrict__ Wlo,
    const float* __restrict__ bias, float* __restrict__ C,
    int N, int K)
{
    extern __shared__ char smem[];
    uint32_t sb = smem_u32(smem);
    int tid = threadIdx.x, wid = tid >> 5, lane = tid & 31;
    int m0 = blockIdx.y * 128, n0 = blockIdx.x * 64;
    int wm = (wid & 3) * 32;          // warp m offset in tile
    int wn = (wid >> 2) * 32;         // warp n offset in tile

    float acc[2][4][4];
#pragma unroll
    for (int i = 0; i < 2; i++)
#pragma unroll
        for (int j = 0; j < 4; j++)
#pragma unroll
            for (int q = 0; q < 4; q++) acc[i][j][q] = 0.f;

    // precomputed ldmatrix shared addresses (byte offsets vary only with ks)
    int lr = lane & 15;
    uint32_t aAddr[2], bAddr[4];
#pragma unroll
    for (int mt = 0; mt < 2; mt++) {
        int row = wm + mt * 16 + lr;
        aAddr[mt] = sb + (uint32_t)(row * (LDSA * 2) + (lane >> 4) * 16);
    }
#pragma unroll
    for (int nt = 0; nt < 4; nt++) {
        int row = wn + nt * 8 + (lr & 7);
        bAddr[nt] = sb + SM_BHI + (uint32_t)(row * (LDSA * 2) + (lr >> 3) * 16);
    }

    for (int k0 = 0; k0 < K; k0 += 64) {
        // stage A (128x64) and B (64x64), hi+lo, padded rows
#pragma unroll
        for (int i = 0; i < 4; i++) {
            int li = tid + i * 256;          // 0..1023
            int r = li >> 3, g = li & 7;
            uint32_t so = (uint32_t)(r * (LDSA * 2) + g * 16);
            size_t goff = (size_t)(m0 + r) * K + k0 + g * 8;
            *(uint4*)(smem + SM_AHI + so) = *(const uint4*)(Ahi + goff);
            *(uint4*)(smem + SM_ALO + so) = *(const uint4*)(Alo + goff);
        }
#pragma unroll
        for (int i = 0; i < 2; i++) {
            int li = tid + i * 256;          // 0..511
            int r = li >> 3, g = li & 7;
            uint32_t so = (uint32_t)(r * (LDSA * 2) + g * 16);
            size_t goff = (size_t)(n0 + r) * K + k0 + g * 8;
            *(uint4*)(smem + SM_BHI + so) = *(const uint4*)(Whi + goff);
            *(uint4*)(smem + SM_BLO + so) = *(const uint4*)(Wlo + goff);
        }
        __syncthreads();

#pragma unroll
        for (int ks = 0; ks < 64; ks += 16) {
            uint32_t ah[2][4], al[2][4], bh[4][2], bl[4][2];
            uint32_t kb = (uint32_t)(ks * 2);
#pragma unroll
            for (int mt = 0; mt < 2; mt++) {
                ldsm_x4(ah[mt], aAddr[mt] + kb);
                ldsm_x4(al[mt], aAddr[mt] + (SM_ALO - SM_AHI) + kb);
            }
#pragma unroll
            for (int nt = 0; nt < 4; nt++) {
                ldsm_x2(bh[nt], bAddr[nt] + kb);
                ldsm_x2(bl[nt], bAddr[nt] + (SM_BLO - SM_BHI) + kb);
            }
#pragma unroll
            for (int mt = 0; mt < 2; mt++)
#pragma unroll
                for (int nt = 0; nt < 4; nt++) {
                    mma16816(acc[mt][nt], ah[mt], bh[nt]);
                    mma16816(acc[mt][nt], ah[mt], bl[nt]);
                    mma16816(acc[mt][nt], al[mt], bh[nt]);
                }
        }
        __syncthreads();
    }

    // epilogue: stage through smem (reuse buffers) for coalesced stores
    float* S = (float*)smem;                 // [128][68]
    const int SW = 68;
    int crow = lane >> 2;                    // 0..7
    int ccol = (lane & 3) * 2;               // 0,2,4,6
#pragma unroll
    for (int mt = 0; mt < 2; mt++)
#pragma unroll
        for (int nt = 0; nt < 4; nt++) {
            int r = wm + mt * 16 + crow;
            int cc = wn + nt * 8 + ccol;
            S[r * SW + cc]           = acc[mt][nt][0];
            S[r * SW + cc + 1]       = acc[mt][nt][1];
            S[(r + 8) * SW + cc]     = acc[mt][nt][2];
            S[(r + 8) * SW + cc + 1] = acc[mt][nt][3];
        }
    __syncthreads();
#pragma unroll
    for (int it = 0; it < 32; it++) {
        int li = tid + it * 256;             // 0..8191
        int cc = li & 63, r = li >> 6;
        int col = n0 + cc;
        if (col < N) {
            float v = S[r * SW + cc];
            if (MODE == 0) v += bias[col];
            size_t o = (size_t)(m0 + r) * N + col;
            if (MODE == 2) v += C[o];
            C[o] = v;
        }
    }
}

// --------------------------- bf16 split helpers ------------------------------
__device__ __forceinline__ void split1(float v, __nv_bfloat16& h, __nv_bfloat16& l) {
    h = __float2bfloat16_rn(v);
    l = __float2bfloat16_rn(v - __bfloat162float(h));
}

__global__ void split_kernel(const float* __restrict__ src,
                             __nv_bfloat16* __restrict__ hi,
                             __nv_bfloat16* __restrict__ lo, int n)
{
    int i = blockIdx.x * blockDim.x + threadIdx.x;
    if (i < n) { __nv_bfloat16 h, l; split1(src[i], h, l); hi[i] = h; lo[i] = l; }
}

// W [K][N] -> Wt hi/lo [Npad][K], Wt[n][k] = W[k][n] (zero-pad n >= N)
__global__ void tsplit_kernel(const float* __restrict__ W,
                              __nv_bfloat16* __restrict__ hi,
                              __nv_bfloat16* __restrict__ lo,
                              int K, int N, int Npad)
{
    int idx = blockIdx.x * blockDim.x + threadIdx.x;
    if (idx >= Npad * K) return;
    int n = idx / K, k = idx % K;
    float v = (n < N) ? W[(size_t)k * N + n] : 0.f;
    __nv_bfloat16 h, l; split1(v, h, l);
    hi[idx] = h; lo[idx] = l;
}

// ------------------------------ rmsnorm (DM=128) -----------------------------
__global__ void rmsnorm128_kernel(const float* __restrict__ src,
                                  const float* __restrict__ w,
                                  __nv_bfloat16* __restrict__ hi,
                                  __nv_bfloat16* __restrict__ lo)
{
    int warp = (blockIdx.x * blockDim.x + threadIdx.x) >> 5;
    int lane = threadIdx.x & 31;
    if (warp >= BT) return;
    const float* row = src + (size_t)warp * DMX;
    float4 v = *(const float4*)(row + lane * 4);
    float ss = v.x*v.x + v.y*v.y + v.z*v.z + v.w*v.w;
#pragma unroll
    for (int o = 16; o; o >>= 1) ss += __shfl_xor_sync(0xffffffffu, ss, o);
    float r = rsqrtf(ss * (1.f / DMX) + EPSF);
    float4 wv = *(const float4*)(w + lane * 4);
    float ov[4] = { v.x*r*wv.x, v.y*r*wv.y, v.z*r*wv.z, v.w*r*wv.w };
    size_t base = (size_t)warp * DMX + lane * 4;
#pragma unroll
    for (int j = 0; j < 4; j++) { __nv_bfloat16 h, l; split1(ov[j], h, l); hi[base+j]=h; lo[base+j]=l; }
}

// ------------------------ causal depthwise conv + silu -----------------------
__global__ void conv_kernel(const float* __restrict__ cw,
                            const float* __restrict__ cb)
{
    int idx = blockIdx.x * blockDim.x + threadIdx.x;   // over BT*CONVD
    if (idx >= BT * CONVD) return;
    int c  = idx % CONVD;
    int bt = idx / CONVD;
    int t = bt % TT;
    int b = bt / TT;
    float acc = cb[c];
#pragma unroll
    for (int k = 0; k < 4; k++) {
        int tt = t - 3 + k;
        if (tt >= 0)
            acc += cw[c * 4 + k] * g_PROJ[(size_t)(b * TT + tt) * PROJD + DINNERX + c];
    }
    g_CONVX[idx] = acc / (1.f + __expf(-acc));   // silu
}

// ------------------------------- dt = softplus -------------------------------
__global__ void dt_kernel(const float* __restrict__ dtb)
{
    int idx = blockIdx.x * blockDim.x + threadIdx.x;   // over BT*NH
    if (idx >= BT * NHX) return;
    int h = idx & 3;
    int bt = idx >> 2;
    int t = bt % TT, b = bt / TT;
    float v = g_PROJ[(size_t)bt * PROJD + DINNERX + CONVD + h] + dtb[h];
    float sp = (v > 20.f) ? v : log1pf(__expf(v));
    g_DT[(b * NHX + h) * TT + t] = sp;
}

// ------------------- within-chunk inclusive cumsum of dt*A -------------------
__global__ void scan_kernel(const float* __restrict__ Alog)
{
    int c = blockIdx.x, bh = blockIdx.y;
    int h = bh & 3;
    int t = threadIdx.x;
    float Ah = -__expf(Alog[h]);
    __shared__ float s[QC];
    int base = bh * TT + c * QC;
    s[t] = g_DT[base + t] * Ah;
    __syncthreads();
#pragma unroll
    for (int off = 1; off < QC; off <<= 1) {
        float v = (t >= off) ? s[t - off] : 0.f;
        __syncthreads();
        s[t] += v;
        __syncthreads();
    }
    g_CUM[base + t] = s[t];
}

// --------------------------- per-chunk local state ---------------------------
__global__ __launch_bounds__(256) void chunkstate_kernel()
{
    int c = blockIdx.x, bh = blockIdx.y;
    int b = bh >> 2, h = bh & 3;
    int tid = threadIdx.x;
    __shared__ float coef[QC];
    __shared__ float Xs[16][HDIMX];
    __shared__ float Bsh[16][NSTATEX];
    int cbase = bh * TT + c * QC;
    size_t rowbase = (size_t)(b * TT + c * QC);
    if (tid < QC) {
        float ce = g_CUM[cbase + QC - 1];
        coef[tid] = __expf(ce - g_CUM[cbase + tid]) * g_DT[cbase + tid];
    }
    float acc[4] = {0.f, 0.f, 0.f, 0.f};
    int p = tid >> 2, ng = (tid & 3) * 4;
    for (int tt = 0; tt < QC; tt += 16) {
        __syncthreads();
#pragma unroll
        for (int j = 0; j < 4; j++) {
            int li = tid + j * 256;
            int r = li >> 6, pp = li & 63;
            Xs[r][pp] = g_CONVX[(rowbase + tt + r) * CONVD + h * 64 + pp];
        }
        {
            int r = tid >> 4, n = tid & 15;
            Bsh[r][n] = g_CONVX[(rowbase + tt + r) * CONVD + 256 + n];
        }
        __syncthreads();
#pragma unroll
        for (int r = 0; r < 16; r++) {
            float cx = coef[tt + r] * Xs[r][p];
#pragma unroll
            for (int j = 0; j < 4; j++) acc[j] += cx * Bsh[r][ng + j];
        }
    }
    size_t dst = ((size_t)bh * NCHK + c) * (HDIMX * NSTATEX) + p * NSTATEX + ng;
    *(float4*)(g_SLOC + dst) = make_float4(acc[0], acc[1], acc[2], acc[3]);
}

// ------------------- chunk-state prefix (16 sequential steps) ----------------
__global__ void prefix_kernel()
{
    int bh = blockIdx.x;
    int i = threadIdx.x * 4;
    float4 s = make_float4(0.f, 0.f, 0.f, 0.f);
    size_t base = (size_t)bh * NCHK * (HDIMX * NSTATEX);
    for (int c = 0; c < NCHK; c++) {
        *(float4*)(g_SIN + base + c * (HDIMX * NSTATEX) + i) = s;
        float dec = __expf(g_CUM[bh * TT + c * QC + QC - 1]);
        float4 sl = *(const float4*)(g_SLOC + base + c * (HDIMX * NSTATEX) + i);
        s.x = s.x * dec + sl.x; s.y = s.y * dec + sl.y;
        s.z = s.z * dec + sl.z; s.w = s.w * dec + sl.w;
    }
}

// ------------------------------ SSD output -----------------------------------
__global__ __launch_bounds__(128) void ssd_out_kernel(const float* __restrict__ Dp)
{
    int c = blockIdx.x, bh = blockIdx.y;
    int b = bh >> 2, h = bh & 3;
    int t = threadIdx.x;
    __shared__ float sX[QC][HDIMX];
    __shared__ float sB[QC][NSTATEX];
    __shared__ float sSin[HDIMX][NSTATEX];
    __shared__ float sCum[QC];
    __shared__ float sDt[QC];
    size_t rowbase = (size_t)(b * TT + c * QC);
    int cbase = bh * TT + c * QC;

    for (int j = 0; j < 64; j++) {
        int li = t + j * 128;
        int r = li >> 6, p = li & 63;
        sX[r][p] = g_CONVX[(rowbase + r) * CONVD + h * 64 + p];
    }
    for (int j = 0; j < 16; j++) {
        int li = t + j * 128;
        int r = li >> 4, n = li & 15;
        sB[r][n] = g_CONVX[(rowbase + r) * CONVD + 256 + n];
    }
    for (int j = 0; j < 8; j++) {
        int li = t + j * 128;
        ((float*)sSin)[li] = g_SIN[((size_t)bh * NCHK + c) * (HDIMX * NSTATEX) + li];
    }
    sCum[t] = g_CUM[cbase + t];
    sDt[t]  = g_DT[cbase + t];
    float Creg[16];
#pragma unroll
    for (int n = 0; n < 16; n++)
        Creg[n] = g_CONVX[(rowbase + t) * CONVD + 272 + n];
    __syncthreads();

    float ct  = sCum[t];
    float ect = __expf(ct);
    float Dh  = Dp[h];
    float y[64];
#pragma unroll
    for (int p = 0; p < 64; p++) {
        float a = 0.f;
#pragma unroll
        for (int n = 0; n < 16; n++) a += Creg[n] * sSin[p][n];
        y[p] = ect * a + Dh * sX[t][p];
    }

    int smax = t | 31;
    for (int s = 0; s <= smax; s++) {
        if (s <= t) {
            float d = 0.f;
#pragma unroll
            for (int n = 0; n < 16; n++) d += Creg[n] * sB[s][n];
            float g = __expf(ct - sCum[s]) * sDt[s] * d;
#pragma unroll
            for (int p = 0; p < 64; p++) y[p] += g * sX[s][p];
        }
    }

    __syncthreads();
#pragma unroll
    for (int p = 0; p < 64; p++) sX[t][p] = y[p];
    __syncthreads();
    for (int j = 0; j < 64; j++) {
        int li = t + j * 128;
        int r = li >> 6, p = li & 63;
        g_Y[(rowbase + r) * DINNERX + h * 64 + p] = sX[r][p];
    }
}

// --------------------------- gated rmsnorm (256) -----------------------------
__global__ void gatednorm_kernel(const float* __restrict__ gnw)
{
    int warp = (blockIdx.x * blockDim.x + threadIdx.x) >> 5;
    int lane = threadIdx.x & 31;
    if (warp >= BT) return;
    const float* yr = g_Y + (size_t)warp * DINNERX;
    const float* gr = g_PROJ + (size_t)warp * PROJD;
    float v[8];
    float ss = 0.f;
#pragma unroll
    for (int i = 0; i < 8; i++) {
        int d = lane * 8 + i;
        float g = gr[d];
        float vv = yr[d] * (g / (1.f + __expf(-g)));
        v[i] = vv;
        ss += vv * vv;
    }
#pragma unroll
    for (int o = 16; o; o >>= 1) ss += __shfl_xor_sync(0xffffffffu, ss, o);
    float r = rsqrtf(ss * (1.f / DINNERX) + EPSF);
    size_t base = (size_t)warp * DINNERX + lane * 8;
#pragma unroll
    for (int i = 0; i < 8; i++) {
        __nv_bfloat16 h, l; split1(v[i] * r * gnw[lane * 8 + i], h, l);
        g_ynhi[base + i] = h; g_ynlo[base + i] = l;
    }
}

// ---------------------------- final pool + head ------------------------------
__global__ void zero_pool_kernel()
{
    int i = blockIdx.x * blockDim.x + threadIdx.x;
    if (i < BB * DMX) g_POOL[i] = 0.f;
}

__global__ __launch_bounds__(128) void pool_kernel(const float* __restrict__ nfw)
{
    int b = blockIdx.y;
    int chunk = blockIdx.x;
    int d = threadIdx.x;
    __shared__ float wsum[4];
    float wnf = nfw[d];
    float acc = 0.f;
    for (int r = 0; r < 64; r++) {
        int t = chunk * 64 + r;
        float v = g_H[(size_t)(b * TT + t) * DMX + d];
        float ss = v * v;
#pragma unroll
        for (int o = 16; o; o >>= 1) ss += __shfl_xor_sync(0xffffffffu, ss, o);
        if ((d & 31) == 0) wsum[d >> 5] = ss;
        __syncthreads();
        float tot = wsum[0] + wsum[1] + wsum[2] + wsum[3];
        __syncthreads();
        acc += v * rsqrtf(tot * (1.f / DMX) + EPSF) * wnf;
    }
    atomicAdd(&g_POOL[b * DMX + d], acc * (1.f / TT));
}

__global__ void final_kernel(const float* __restrict__ ow,
                             const float* __restrict__ ob,
                             float* __restrict__ out)
{
    int b = blockIdx.x;
    int j = threadIdx.x;
    __shared__ float p[DMX];
    if (j < DMX) p[j] = g_POOL[b * DMX + j];
    __syncthreads();
    float acc = ob[j];
#pragma unroll 4
    for (int k = 0; k < DMX; k++) acc += p[k] * ow[k * DIMX + j];
    out[b * DIMX + j] = acc;
}

// ------------------------------ launcher -------------------------------------
extern "C" void kernel_launch(void* const* d_in, const int* in_sizes, int n_in,
                              void* d_out, int out_size)
{
    const float* x         = (const float*)d_in[0];
    const float* in_w      = (const float*)d_in[1];
    const float* in_b      = (const float*)d_in[2];
    const float* norm_w    = (const float*)d_in[3];
    const float* inproj_w  = (const float*)d_in[4];
    const float* conv_w    = (const float*)d_in[5];
    const float* conv_b    = (const float*)d_in[6];
    const float* A_log     = (const float*)d_in[7];
    const float* Dparam    = (const float*)d_in[8];
    const float* dt_bias   = (const float*)d_in[9];
    const float* gnorm_w   = (const float*)d_in[10];
    const float* outproj_w = (const float*)d_in[11];
    const float* normf_w   = (const float*)d_in[12];
    const float* out_w     = (const float*)d_in[13];
    const float* out_b     = (const float*)d_in[14];

    float *pH, *pPROJ;
    __nv_bfloat16 *pXhi, *pXlo, *pHNhi, *pHNlo, *pYNhi, *pYNlo;
    __nv_bfloat16 *pW1hi, *pW1lo, *pW2hi, *pW2lo, *pW3hi, *pW3lo;
    cudaGetSymbolAddress((void**)&pH,    g_H);
    cudaGetSymbolAddress((void**)&pPROJ, g_PROJ);
    cudaGetSymbolAddress((void**)&pXhi,  g_xhi);
    cudaGetSymbolAddress((void**)&pXlo,  g_xlo);
    cudaGetSymbolAddress((void**)&pHNhi, g_hnhi);
    cudaGetSymbolAddress((void**)&pHNlo, g_hnlo);
    cudaGetSymbolAddress((void**)&pYNhi, g_ynhi);
    cudaGetSymbolAddress((void**)&pYNlo, g_ynlo);
    cudaGetSymbolAddress((void**)&pW1hi, g_w1hi);
    cudaGetSymbolAddress((void**)&pW1lo, g_w1lo);
    cudaGetSymbolAddress((void**)&pW2hi, g_w2hi);
    cudaGetSymbolAddress((void**)&pW2lo, g_w2lo);
    cudaGetSymbolAddress((void**)&pW3hi, g_w3hi);
    cudaGetSymbolAddress((void**)&pW3lo, g_w3lo);

    cudaFuncSetAttribute(mma_gemm<0>, cudaFuncAttributeMaxDynamicSharedMemorySize, SM_TOTAL);
    cudaFuncSetAttribute(mma_gemm<1>, cudaFuncAttributeMaxDynamicSharedMemorySize, SM_TOTAL);
    cudaFuncSetAttribute(mma_gemm<2>, cudaFuncAttributeMaxDynamicSharedMemorySize, SM_TOTAL);

    // weight conversions
    tsplit_kernel<<<(DMX * DIMX + 255) / 256, 256>>>(in_w, pW1hi, pW1lo, DIMX, DMX, DMX);
    for (int l = 0; l < LNUM; l++) {
        tsplit_kernel<<<(PROJPAD * DMX + 255) / 256, 256>>>(
            inproj_w + (size_t)l * DMX * PROJD,
            pW2hi + (size_t)l * PROJPAD * DMX, pW2lo + (size_t)l * PROJPAD * DMX,
            DMX, PROJD, PROJPAD);
        tsplit_kernel<<<(DMX * DINNERX + 255) / 256, 256>>>(
            outproj_w + (size_t)l * DINNERX * DMX,
            pW3hi + (size_t)l * DMX * DINNERX, pW3lo + (size_t)l * DMX * DINNERX,
            DINNERX, DMX, DMX);
    }
    // x split
    split_kernel<<<(BT * DIMX + 255) / 256, 256>>>(x, pXhi, pXlo, BT * DIMX);

    // h = x @ in_w + in_b
    mma_gemm<0><<<dim3(DMX / 64, BT / 128), 256, SM_TOTAL>>>(
        pXhi, pXlo, pW1hi, pW1lo, in_b, pH, DMX, DIMX);

    for (int l = 0; l < LNUM; l++) {
        rmsnorm128_kernel<<<BT / 8, 256>>>(pH, norm_w + l * DMX, pHNhi, pHNlo);
        mma_gemm<1><<<dim3(PROJPAD / 64, BT / 128), 256, SM_TOTAL>>>(
            pHNhi, pHNlo,
            pW2hi + (size_t)l * PROJPAD * DMX, pW2lo + (size_t)l * PROJPAD * DMX,
            nullptr, pPROJ, PROJD, DMX);
        conv_kernel<<<(BT * CONVD + 255) / 256, 256>>>(
            conv_w + l * CONVD * 4, conv_b + l * CONVD);
        dt_kernel<<<(BT * NHX) / 256, 256>>>(dt_bias + l * NHX);
        scan_kernel<<<dim3(NCHK, BHX), QC>>>(A_log + l * NHX);
        chunkstate_kernel<<<dim3(NCHK, BHX), 256>>>();
        prefix_kernel<<<BHX, 256>>>();
        ssd_out_kernel<<<dim3(NCHK, BHX), QC>>>(Dparam + l * NHX);
        gatednorm_kernel<<<BT / 8, 256>>>(gnorm_w + l * DINNERX);
        mma_gemm<2><<<dim3(DMX / 64, BT / 128), 256, SM_TOTAL>>>(
            pYNhi, pYNlo,
            pW3hi + (size_t)l * DMX * DINNERX, pW3lo + (size_t)l * DMX * DINNERX,
            nullptr, pH, DMX, DINNERX);
    }

    zero_pool_kernel<<<4, 256>>>();
    pool_kernel<<<dim3(32, BB), DMX>>>(normf_w);
    final_kernel<<<BB, DIMX>>>(out_w, out_b, (float*)d_out);
}

// round 5
// speedup vs baseline: 1.1895x; 1.0192x over previous
#include <cuda_runtime.h>
#include <cuda_bf16.h>
#include <math.h>
#include <stdint.h>

#define BB 8
#define TT 2048
#define DIMX 512
#define DMX 128
#define DINNERX 256
#define NSTATEX 16
#define HDIMX 64
#define NHX 4
#define CONVD 288
#define PROJD 548
#define PROJPAD 576
#define LNUM 2
#define BT (BB*TT)          // 16384
#define QC 128              // chunk length
#define NCHK (TT/QC)        // 16
#define BHX (BB*NHX)        // 32
#define EPSF 1e-5f

// ------------------------- scratch (static device memory) -------------------
__device__ float g_H[BT*DMX];
__device__ float g_PROJ[BT*PROJD];
__device__ float g_CONVX[BT*CONVD];
__device__ float g_DT[BHX*TT];
__device__ float g_CUM[BHX*TT];
__device__ float g_SLOC[BHX*NCHK*HDIMX*NSTATEX];
__device__ float g_SIN[BHX*NCHK*HDIMX*NSTATEX];
__device__ float g_Y[BT*DINNERX];
__device__ float g_POOL[BB*DMX];

__device__ __nv_bfloat16 g_xhi[BT*DIMX],    g_xlo[BT*DIMX];
__device__ __nv_bfloat16 g_hnhi[BT*DMX],    g_hnlo[BT*DMX];
__device__ __nv_bfloat16 g_ynhi[BT*DINNERX],g_ynlo[BT*DINNERX];
__device__ __nv_bfloat16 g_w1hi[DMX*DIMX],  g_w1lo[DMX*DIMX];
__device__ __nv_bfloat16 g_w2hi[LNUM*PROJPAD*DMX], g_w2lo[LNUM*PROJPAD*DMX];
__device__ __nv_bfloat16 g_w3hi[LNUM*DMX*DINNERX], g_w3lo[LNUM*DMX*DINNERX];

// ------------------------------ PTX helpers ---------------------------------
__device__ __forceinline__ uint32_t smem_u32(const void* p) {
    uint32_t a;
    asm("{ .reg .u64 t; cvta.to.shared.u64 t, %1; cvt.u32.u64 %0, t; }" : "=r"(a) : "l"(p));
    return a;
}
__device__ __forceinline__ void ldsm_x4(uint32_t* r, uint32_t addr) {
    asm volatile("ldmatrix.sync.aligned.m8n8.x4.shared.b16 {%0,%1,%2,%3}, [%4];"
        : "=r"(r[0]), "=r"(r[1]), "=r"(r[2]), "=r"(r[3]) : "r"(addr));
}
__device__ __forceinline__ void ldsm_x2(uint32_t* r, uint32_t addr) {
    asm volatile("ldmatrix.sync.aligned.m8n8.x2.shared.b16 {%0,%1}, [%2];"
        : "=r"(r[0]), "=r"(r[1]) : "r"(addr));
}
__device__ __forceinline__ void mma16816(float* c, const uint32_t* a, const uint32_t* b) {
    asm volatile("mma.sync.aligned.m16n8k16.row.col.f32.bf16.bf16.f32 "
        "{%0,%1,%2,%3}, {%4,%5,%6,%7}, {%8,%9}, {%0,%1,%2,%3};"
        : "+f"(c[0]), "+f"(c[1]), "+f"(c[2]), "+f"(c[3])
        : "r"(a[0]), "r"(a[1]), "r"(a[2]), "r"(a[3]), "r"(b[0]), "r"(b[1]));
}
__device__ __forceinline__ void cp16(uint32_t saddr, const void* g) {
    asm volatile("cp.async.ca.shared.global [%0], [%1], 16;" :: "r"(saddr), "l"(g));
}
__device__ __forceinline__ void cp_commit() {
    asm volatile("cp.async.commit_group;" ::: "memory");
}
template<int N> __device__ __forceinline__ void cp_wait() {
    asm volatile("cp.async.wait_group %0;" :: "n"(N) : "memory");
}

// ------------------------------ HMMA GEMM ------------------------------------
// C[M,N] = A[M,K] @ W[K,N], A bf16 hi/lo [M][K], W as Wt hi/lo [Npad][K].
// Block 128x64, 8 warps 32x32, K staged 64, double-buffered cp.async pipeline.
// MODE 0: C = D + bias ; 1: C = D ; 2: C += D.
#define LDSA 72
#define A_BYTES (128*LDSA*2)               // 18432
#define B_BYTES (64*LDSA*2)                // 9216
#define OFF_ALO A_BYTES
#define OFF_BHI (2*A_BYTES)
#define OFF_BLO (2*A_BYTES + B_BYTES)
#define STAGE_BYTES (2*A_BYTES + 2*B_BYTES) // 55296
#define SM_TOTAL (2*STAGE_BYTES)            // 110592

template<int MODE>
__global__ __launch_bounds__(256, 2) void mma_gemm(
    const __nv_bfloat16* __restrict__ Ahi, const __nv_bfloat16* __restrict__ Alo,
    const __nv_bfloat16* __restrict__ Whi, const __nv_bfloat16* __restrict__ Wlo,
    const float* __restrict__ bias, float* __restrict__ C,
    int N, int K)
{
    extern __shared__ char smem[];
    uint32_t sb = smem_u32(smem);
    int tid = threadIdx.x, wid = tid >> 5, lane = tid & 31;
    int m0 = blockIdx.y * 128, n0 = blockIdx.x * 64;
    int wm = (wid & 3) * 32, wn = (wid >> 2) * 32;

    float acc[2][4][4];
#pragma unroll
    for (int i = 0; i < 2; i++)
#pragma unroll
        for (int j = 0; j < 4; j++)
#pragma unroll
            for (int q = 0; q < 4; q++) acc[i][j][q] = 0.f;

    // per-thread load offsets (within a stage)
    int lar = tid >> 1, lag = (tid & 1) * 4;  // not used; use chunk scheme below

    // ldmatrix intra-stage offsets
    int lr = lane & 15;
    uint32_t aOff[2], bOff[4];
#pragma unroll
    for (int mt = 0; mt < 2; mt++)
        aOff[mt] = (uint32_t)((wm + mt * 16 + lr) * (LDSA * 2) + (lane >> 4) * 16);
#pragma unroll
    for (int nt = 0; nt < 4; nt++)
        bOff[nt] = (uint32_t)(OFF_BHI + (wn + nt * 8 + (lr & 7)) * (LDSA * 2) + ((lr >> 3) & 1) * 16);

    int nstage = K >> 6;

    // ---- stage loader (cp.async) ----
    auto load_stage = [&](int buf, int k0) {
        uint32_t base = sb + buf * STAGE_BYTES;
#pragma unroll
        for (int i = 0; i < 4; i++) {
            int li = tid + i * 256;               // 1024 chunks for A
            int r = li >> 3, g8 = li & 7;
            uint32_t so = (uint32_t)(r * (LDSA * 2) + g8 * 16);
            size_t goff = (size_t)(m0 + r) * K + k0 + g8 * 8;
            cp16(base + so, Ahi + goff);
            cp16(base + OFF_ALO + so, Alo + goff);
        }
#pragma unroll
        for (int i = 0; i < 2; i++) {
            int li = tid + i * 256;               // 512 chunks for B
            int r = li >> 3, g8 = li & 7;
            uint32_t so = (uint32_t)(r * (LDSA * 2) + g8 * 16);
            size_t goff = (size_t)(n0 + r) * K + k0 + g8 * 8;
            cp16(base + OFF_BHI + so, Whi + goff);
            cp16(base + OFF_BLO + so, Wlo + goff);
        }
    };

    load_stage(0, 0);
    cp_commit();

    for (int s = 0; s < nstage; s++) {
        if (s + 1 < nstage) load_stage((s + 1) & 1, (s + 1) * 64);
        cp_commit();
        if (s + 1 < nstage) cp_wait<1>(); else cp_wait<0>();
        __syncthreads();

        uint32_t sbuf = sb + (s & 1) * STAGE_BYTES;
#pragma unroll
        for (int ks = 0; ks < 64; ks += 16) {
            uint32_t kb = (uint32_t)(ks * 2);
            uint32_t ah[2][4], al[2][4], bh[4][2], bl[4][2];
#pragma unroll
            for (int mt = 0; mt < 2; mt++) {
                ldsm_x4(ah[mt], sbuf + aOff[mt] + kb);
                ldsm_x4(al[mt], sbuf + OFF_ALO + aOff[mt] + kb);
            }
#pragma unroll
            for (int nt = 0; nt < 4; nt++) {
                ldsm_x2(bh[nt], sbuf + bOff[nt] + kb);
                ldsm_x2(bl[nt], sbuf + bOff[nt] + B_BYTES + kb);
            }
#pragma unroll
            for (int mt = 0; mt < 2; mt++)
#pragma unroll
                for (int nt = 0; nt < 4; nt++) {
                    mma16816(acc[mt][nt], ah[mt], bh[nt]);
                    mma16816(acc[mt][nt], ah[mt], bl[nt]);
                    mma16816(acc[mt][nt], al[mt], bh[nt]);
                }
        }
        __syncthreads();
    }

    // epilogue via smem for coalesced stores
    float* S = (float*)smem;          // [128][68]
    const int SW = 68;
    int crow = lane >> 2, ccol = (lane & 3) * 2;
#pragma unroll
    for (int mt = 0; mt < 2; mt++)
#pragma unroll
        for (int nt = 0; nt < 4; nt++) {
            int r = wm + mt * 16 + crow;
            int cc = wn + nt * 8 + ccol;
            S[r * SW + cc]           = acc[mt][nt][0];
            S[r * SW + cc + 1]       = acc[mt][nt][1];
            S[(r + 8) * SW + cc]     = acc[mt][nt][2];
            S[(r + 8) * SW + cc + 1] = acc[mt][nt][3];
        }
    __syncthreads();
#pragma unroll
    for (int it = 0; it < 32; it++) {
        int li = tid + it * 256;
        int cc = li & 63, r = li >> 6;
        int col = n0 + cc;
        if (col < N) {
            float v = S[r * SW + cc];
            if (MODE == 0) v += bias[col];
            size_t o = (size_t)(m0 + r) * N + col;
            if (MODE == 2) v += C[o];
            C[o] = v;
        }
    }
}

// --------------------------- bf16 split helpers ------------------------------
__device__ __forceinline__ void split1(float v, __nv_bfloat16& h, __nv_bfloat16& l) {
    h = __float2bfloat16_rn(v);
    l = __float2bfloat16_rn(v - __bfloat162float(h));
}

__global__ void split_kernel(const float* __restrict__ src,
                             __nv_bfloat16* __restrict__ hi,
                             __nv_bfloat16* __restrict__ lo, int n)
{
    int i = blockIdx.x * blockDim.x + threadIdx.x;
    if (i < n) { __nv_bfloat16 h, l; split1(src[i], h, l); hi[i] = h; lo[i] = l; }
}

__global__ void tsplit_kernel(const float* __restrict__ W,
                              __nv_bfloat16* __restrict__ hi,
                              __nv_bfloat16* __restrict__ lo,
                              int K, int N, int Npad)
{
    int idx = blockIdx.x * blockDim.x + threadIdx.x;
    if (idx >= Npad * K) return;
    int n = idx / K, k = idx % K;
    float v = (n < N) ? W[(size_t)k * N + n] : 0.f;
    __nv_bfloat16 h, l; split1(v, h, l);
    hi[idx] = h; lo[idx] = l;
}

// ------------------------------ rmsnorm (DM=128) -----------------------------
__global__ void rmsnorm128_kernel(const float* __restrict__ src,
                                  const float* __restrict__ w,
                                  __nv_bfloat16* __restrict__ hi,
                                  __nv_bfloat16* __restrict__ lo)
{
    int warp = (blockIdx.x * blockDim.x + threadIdx.x) >> 5;
    int lane = threadIdx.x & 31;
    if (warp >= BT) return;
    const float* row = src + (size_t)warp * DMX;
    float4 v = *(const float4*)(row + lane * 4);
    float ss = v.x*v.x + v.y*v.y + v.z*v.z + v.w*v.w;
#pragma unroll
    for (int o = 16; o; o >>= 1) ss += __shfl_xor_sync(0xffffffffu, ss, o);
    float r = rsqrtf(ss * (1.f / DMX) + EPSF);
    float4 wv = *(const float4*)(w + lane * 4);
    float ov[4] = { v.x*r*wv.x, v.y*r*wv.y, v.z*r*wv.z, v.w*r*wv.w };
    size_t base = (size_t)warp * DMX + lane * 4;
#pragma unroll
    for (int j = 0; j < 4; j++) { __nv_bfloat16 h, l; split1(ov[j], h, l); hi[base+j]=h; lo[base+j]=l; }
}

// ------------------------ causal conv + silu (sliding window) ----------------
__global__ __launch_bounds__(288) void conv_kernel(const float* __restrict__ cw,
                                                   const float* __restrict__ cb)
{
    int b = blockIdx.y;
    int t0 = blockIdx.x * 64;
    int c = threadIdx.x;                 // 0..287
    float w0 = cw[c*4], w1 = cw[c*4+1], w2 = cw[c*4+2], w3 = cw[c*4+3];
    float bias = cb[c];
    size_t base = (size_t)(b * TT) * PROJD + DINNERX + c;
    float xm3 = 0.f, xm2 = 0.f, xm1 = 0.f;
    if (t0 >= 3) {
        xm3 = g_PROJ[base + (size_t)(t0-3) * PROJD];
        xm2 = g_PROJ[base + (size_t)(t0-2) * PROJD];
        xm1 = g_PROJ[base + (size_t)(t0-1) * PROJD];
    }
#pragma unroll 4
    for (int t = t0; t < t0 + 64; t++) {
        float xt = g_PROJ[base + (size_t)t * PROJD];
        float a = bias + w0*xm3 + w1*xm2 + w2*xm1 + w3*xt;
        g_CONVX[(size_t)(b * TT + t) * CONVD + c] = a / (1.f + __expf(-a));
        xm3 = xm2; xm2 = xm1; xm1 = xt;
    }
}

// ---------------- softplus(dt) + within-chunk cumsum (fused) -----------------
__global__ void scan_kernel(const float* __restrict__ Alog,
                            const float* __restrict__ dtb)
{
    int c = blockIdx.x, bh = blockIdx.y;
    int h = bh & 3, b = bh >> 2;
    int t = threadIdx.x;
    int gt = c * QC + t;
    float v = g_PROJ[(size_t)(b * TT + gt) * PROJD + DINNERX + CONVD + h] + dtb[h];
    float sp = (v > 20.f) ? v : log1pf(__expf(v));
    int base = bh * TT + c * QC;
    g_DT[base + t] = sp;
    float Ah = -__expf(Alog[h]);
    __shared__ float s[QC];
    s[t] = sp * Ah;
    __syncthreads();
#pragma unroll
    for (int off = 1; off < QC; off <<= 1) {
        float x = (t >= off) ? s[t - off] : 0.f;
        __syncthreads();
        s[t] += x;
        __syncthreads();
    }
    g_CUM[base + t] = s[t];
}

// --------------------------- per-chunk local state ---------------------------
__global__ __launch_bounds__(256) void chunkstate_kernel()
{
    int c = blockIdx.x, bh = blockIdx.y;
    int b = bh >> 2, h = bh & 3;
    int tid = threadIdx.x;
    __shared__ float coef[QC];
    __shared__ float Xs[16][HDIMX];
    __shared__ float Bsh[16][NSTATEX];
    int cbase = bh * TT + c * QC;
    size_t rowbase = (size_t)(b * TT + c * QC);
    if (tid < QC) {
        float ce = g_CUM[cbase + QC - 1];
        coef[tid] = __expf(ce - g_CUM[cbase + tid]) * g_DT[cbase + tid];
    }
    float acc[4] = {0.f, 0.f, 0.f, 0.f};
    int p = tid >> 2, ng = (tid & 3) * 4;
    for (int tt = 0; tt < QC; tt += 16) {
        __syncthreads();
#pragma unroll
        for (int j = 0; j < 4; j++) {
            int li = tid + j * 256;
            int r = li >> 6, pp = li & 63;
            Xs[r][pp] = g_CONVX[(rowbase + tt + r) * CONVD + h * 64 + pp];
        }
        {
            int r = tid >> 4, n = tid & 15;
            Bsh[r][n] = g_CONVX[(rowbase + tt + r) * CONVD + 256 + n];
        }
        __syncthreads();
#pragma unroll
        for (int r = 0; r < 16; r++) {
            float cx = coef[tt + r] * Xs[r][p];
#pragma unroll
            for (int j = 0; j < 4; j++) acc[j] += cx * Bsh[r][ng + j];
        }
    }
    size_t dst = ((size_t)bh * NCHK + c) * (HDIMX * NSTATEX) + p * NSTATEX + ng;
    *(float4*)(g_SLOC + dst) = make_float4(acc[0], acc[1], acc[2], acc[3]);
}

// ------------------- chunk-state prefix (prefetched) -------------------------
__global__ __launch_bounds__(256) void prefix_kernel()
{
    int bh = blockIdx.x;
    int i = threadIdx.x * 4;
    size_t base = (size_t)bh * NCHK * (HDIMX * NSTATEX);
    float4 sl[NCHK];
    float dec[NCHK];
#pragma unroll
    for (int c = 0; c < NCHK; c++)
        sl[c] = *(const float4*)(g_SLOC + base + c * (HDIMX * NSTATEX) + i);
#pragma unroll
    for (int c = 0; c < NCHK; c++)
        dec[c] = g_CUM[bh * TT + c * QC + QC - 1];
#pragma unroll
    for (int c = 0; c < NCHK; c++) dec[c] = __expf(dec[c]);
    float4 s = make_float4(0.f, 0.f, 0.f, 0.f);
#pragma unroll
    for (int c = 0; c < NCHK; c++) {
        *(float4*)(g_SIN + base + c * (HDIMX * NSTATEX) + i) = s;
        s.x = s.x * dec[c] + sl[c].x; s.y = s.y * dec[c] + sl[c].y;
        s.z = s.z * dec[c] + sl[c].z; s.w = s.w * dec[c] + sl[c].w;
    }
}

// ------------------------------ SSD output (float4) --------------------------
__global__ __launch_bounds__(128) void ssd_out_kernel(const float* __restrict__ Dp)
{
    int c = blockIdx.x, bh = blockIdx.y;
    int b = bh >> 2, h = bh & 3;
    int t = threadIdx.x;
    __shared__ float4 sX[QC][16];          // 32 KB
    __shared__ float4 sB4[QC][4];          //  8 KB
    __shared__ float4 sSin[HDIMX][4];      //  4 KB
    __shared__ float sCum[QC];
    __shared__ float sDt[QC];
    size_t rowbase = (size_t)(b * TT + c * QC);
    int cbase = bh * TT + c * QC;

#pragma unroll
    for (int j = 0; j < 16; j++) {
        int li = t + j * 128;
        int r = li >> 4, p4 = li & 15;
        sX[r][p4] = *(const float4*)(g_CONVX + (rowbase + r) * CONVD + h * 64 + p4 * 4);
    }
#pragma unroll
    for (int j = 0; j < 4; j++) {
        int li = t + j * 128;
        int r = li >> 2, n4 = li & 3;
        sB4[r][n4] = *(const float4*)(g_CONVX + (rowbase + r) * CONVD + 256 + n4 * 4);
    }
#pragma unroll
    for (int j = 0; j < 2; j++) {
        int li = t + j * 128;
        int p = li >> 2, n4 = li & 3;
        sSin[p][n4] = *(const float4*)(g_SIN + ((size_t)bh * NCHK + c) * (HDIMX * NSTATEX) + p * NSTATEX + n4 * 4);
    }
    sCum[t] = g_CUM[cbase + t];
    sDt[t]  = g_DT[cbase + t];
    float4 c4[4];
#pragma unroll
    for (int n4 = 0; n4 < 4; n4++)
        c4[n4] = *(const float4*)(g_CONVX + (rowbase + t) * CONVD + 272 + n4 * 4);
    __syncthreads();

    float ct  = sCum[t];
    float ect = __expf(ct);
    float Dh  = Dp[h];
    float4 y4[16];
#pragma unroll
    for (int p4 = 0; p4 < 16; p4++) {
        float a0 = 0.f, a1 = 0.f, a2 = 0.f, a3 = 0.f;
#pragma unroll
        for (int n4 = 0; n4 < 4; n4++) {
            float4 cc = c4[n4];
            float4 s0 = sSin[p4*4+0][n4], s1 = sSin[p4*4+1][n4];
            float4 s2 = sSin[p4*4+2][n4], s3 = sSin[p4*4+3][n4];
            a0 += cc.x*s0.x + cc.y*s0.y + cc.z*s0.z + cc.w*s0.w;
            a1 += cc.x*s1.x + cc.y*s1.y + cc.z*s1.z + cc.w*s1.w;
            a2 += cc.x*s2.x + cc.y*s2.y + cc.z*s2.z + cc.w*s2.w;
            a3 += cc.x*s3.x + cc.y*s3.y + cc.z*s3.z + cc.w*s3.w;
        }
        float4 xv = sX[t][p4];
        y4[p4].x = ect * a0 + Dh * xv.x;
        y4[p4].y = ect * a1 + Dh * xv.y;
        y4[p4].z = ect * a2 + Dh * xv.z;
        y4[p4].w = ect * a3 + Dh * xv.w;
    }

    int smax = t | 31;
    for (int s = 0; s <= smax; s++) {
        if (s <= t) {
            float d = 0.f;
#pragma unroll
            for (int n4 = 0; n4 < 4; n4++) {
                float4 cc = c4[n4], bb = sB4[s][n4];
                d += cc.x*bb.x + cc.y*bb.y + cc.z*bb.z + cc.w*bb.w;
            }
            float g = __expf(ct - sCum[s]) * sDt[s] * d;
#pragma unroll
            for (int p4 = 0; p4 < 16; p4++) {
                float4 xv = sX[s][p4];
                y4[p4].x += g * xv.x; y4[p4].y += g * xv.y;
                y4[p4].z += g * xv.z; y4[p4].w += g * xv.w;
            }
        }
    }

    __syncthreads();
#pragma unroll
    for (int p4 = 0; p4 < 16; p4++) sX[t][p4] = y4[p4];
    __syncthreads();
#pragma unroll
    for (int j = 0; j < 16; j++) {
        int li = t + j * 128;
        int r = li >> 4, p4 = li & 15;
        *(float4*)(g_Y + (rowbase + r) * DINNERX + h * 64 + p4 * 4) = sX[r][p4];
    }
}

// --------------------------- gated rmsnorm -----------------------------------
__global__ void gatednorm_kernel(const float* __restrict__ gnw)
{
    int warp = (blockIdx.x * blockDim.x + threadIdx.x) >> 5;
    int lane = threadIdx.x & 31;
    if (warp >= BT) return;
    const float* yr = g_Y + (size_t)warp * DINNERX;
    const float* gr = g_PROJ + (size_t)warp * PROJD;
    float v[8];
    float ss = 0.f;
#pragma unroll
    for (int i = 0; i < 8; i++) {
        int d = lane * 8 + i;
        float g = gr[d];
        float vv = yr[d] * (g / (1.f + __expf(-g)));
        v[i] = vv;
        ss += vv * vv;
    }
#pragma unroll
    for (int o = 16; o; o >>= 1) ss += __shfl_xor_sync(0xffffffffu, ss, o);
    float r = rsqrtf(ss * (1.f / DINNERX) + EPSF);
    size_t base = (size_t)warp * DINNERX + lane * 8;
#pragma unroll
    for (int i = 0; i < 8; i++) {
        __nv_bfloat16 h, l; split1(v[i] * r * gnw[lane * 8 + i], h, l);
        g_ynhi[base + i] = h; g_ynlo[base + i] = l;
    }
}

// ---------------------------- final pool + head ------------------------------
__global__ void zero_pool_kernel()
{
    int i = blockIdx.x * blockDim.x + threadIdx.x;
    if (i < BB * DMX) g_POOL[i] = 0.f;
}

__global__ __launch_bounds__(128) void pool_kernel(const float* __restrict__ nfw)
{
    int b = blockIdx.y;
    int chunk = blockIdx.x;
    int d = threadIdx.x;
    __shared__ float wsum[4];
    float wnf = nfw[d];
    float acc = 0.f;
    for (int r = 0; r < 64; r++) {
        int t = chunk * 64 + r;
        float v = g_H[(size_t)(b * TT + t) * DMX + d];
        float ss = v * v;
#pragma unroll
        for (int o = 16; o; o >>= 1) ss += __shfl_xor_sync(0xffffffffu, ss, o);
        if ((d & 31) == 0) wsum[d >> 5] = ss;
        __syncthreads();
        float tot = wsum[0] + wsum[1] + wsum[2] + wsum[3];
        __syncthreads();
        acc += v * rsqrtf(tot * (1.f / DMX) + EPSF) * wnf;
    }
    atomicAdd(&g_POOL[b * DMX + d], acc * (1.f / TT));
}

__global__ void final_kernel(const float* __restrict__ ow,
                             const float* __restrict__ ob,
                             float* __restrict__ out)
{
    int b = blockIdx.x;
    int j = threadIdx.x;
    __shared__ float p[DMX];
    if (j < DMX) p[j] = g_POOL[b * DMX + j];
    __syncthreads();
    float acc = ob[j];
#pragma unroll 4
    for (int k = 0; k < DMX; k++) acc += p[k] * ow[k * DIMX + j];
    out[b * DIMX + j] = acc;
}

// ------------------------------ launcher -------------------------------------
extern "C" void kernel_launch(void* const* d_in, const int* in_sizes, int n_in,
                              void* d_out, int out_size)
{
    const float* x         = (const float*)d_in[0];
    const float* in_w      = (const float*)d_in[1];
    const float* in_b      = (const float*)d_in[2];
    const float* norm_w    = (const float*)d_in[3];
    const float* inproj_w  = (const float*)d_in[4];
    const float* conv_w    = (const float*)d_in[5];
    const float* conv_b    = (const float*)d_in[6];
    const float* A_log     = (const float*)d_in[7];
    const float* Dparam    = (const float*)d_in[8];
    const float* dt_bias   = (const float*)d_in[9];
    const float* gnorm_w   = (const float*)d_in[10];
    const float* outproj_w = (const float*)d_in[11];
    const float* normf_w   = (const float*)d_in[12];
    const float* out_w     = (const float*)d_in[13];
    const float* out_b     = (const float*)d_in[14];

    float *pH, *pPROJ;
    __nv_bfloat16 *pXhi, *pXlo, *pHNhi, *pHNlo, *pYNhi, *pYNlo;
    __nv_bfloat16 *pW1hi, *pW1lo, *pW2hi, *pW2lo, *pW3hi, *pW3lo;
    cudaGetSymbolAddress((void**)&pH,    g_H);
    cudaGetSymbolAddress((void**)&pPROJ, g_PROJ);
    cudaGetSymbolAddress((void**)&pXhi,  g_xhi);
    cudaGetSymbolAddress((void**)&pXlo,  g_xlo);
    cudaGetSymbolAddress((void**)&pHNhi, g_hnhi);
    cudaGetSymbolAddress((void**)&pHNlo, g_hnlo);
    cudaGetSymbolAddress((void**)&pYNhi, g_ynhi);
    cudaGetSymbolAddress((void**)&pYNlo, g_ynlo);
    cudaGetSymbolAddress((void**)&pW1hi, g_w1hi);
    cudaGetSymbolAddress((void**)&pW1lo, g_w1lo);
    cudaGetSymbolAddress((void**)&pW2hi, g_w2hi);
    cudaGetSymbolAddress((void**)&pW2lo, g_w2lo);
    cudaGetSymbolAddress((void**)&pW3hi, g_w3hi);
    cudaGetSymbolAddress((void**)&pW3lo, g_w3lo);

    cudaFuncSetAttribute(mma_gemm<0>, cudaFuncAttributeMaxDynamicSharedMemorySize, SM_TOTAL);
    cudaFuncSetAttribute(mma_gemm<1>, cudaFuncAttributeMaxDynamicSharedMemorySize, SM_TOTAL);
    cudaFuncSetAttribute(mma_gemm<2>, cudaFuncAttributeMaxDynamicSharedMemorySize, SM_TOTAL);

    // prep (ordered so a real GEMM lands near the ncu -s 5 window)
    split_kernel<<<(BT * DIMX + 255) / 256, 256>>>(x, pXhi, pXlo, BT * DIMX);
    tsplit_kernel<<<(DMX * DIMX + 255) / 256, 256>>>(in_w, pW1hi, pW1lo, DIMX, DMX, DMX);
    tsplit_kernel<<<(PROJPAD * DMX + 255) / 256, 256>>>(
        inproj_w, pW2hi, pW2lo, DMX, PROJD, PROJPAD);
    tsplit_kernel<<<(DMX * DINNERX + 255) / 256, 256>>>(
        outproj_w, pW3hi, pW3lo, DINNERX, DMX, DMX);
    tsplit_kernel<<<(PROJPAD * DMX + 255) / 256, 256>>>(
        inproj_w + (size_t)DMX * PROJD,
        pW2hi + (size_t)PROJPAD * DMX, pW2lo + (size_t)PROJPAD * DMX,
        DMX, PROJD, PROJPAD);

    // h = x @ in_w + in_b   (launch idx 5)
    mma_gemm<0><<<dim3(DMX / 64, BT / 128), 256, SM_TOTAL>>>(
        pXhi, pXlo, pW1hi, pW1lo, in_b, pH, DMX, DIMX);

    tsplit_kernel<<<(DMX * DINNERX + 255) / 256, 256>>>(
        outproj_w + (size_t)DINNERX * DMX,
        pW3hi + (size_t)DMX * DINNERX, pW3lo + (size_t)DMX * DINNERX,
        DINNERX, DMX, DMX);

    for (int l = 0; l < LNUM; l++) {
        rmsnorm128_kernel<<<BT / 8, 256>>>(pH, norm_w + l * DMX, pHNhi, pHNlo);
        mma_gemm<1><<<dim3(PROJPAD / 64, BT / 128), 256, SM_TOTAL>>>(
            pHNhi, pHNlo,
            pW2hi + (size_t)l * PROJPAD * DMX, pW2lo + (size_t)l * PROJPAD * DMX,
            nullptr, pPROJ, PROJD, DMX);
        conv_kernel<<<dim3(TT / 64, BB), 288>>>(
            conv_w + l * CONVD * 4, conv_b + l * CONVD);
        scan_kernel<<<dim3(NCHK, BHX), QC>>>(A_log + l * NHX, dt_bias + l * NHX);
        chunkstate_kernel<<<dim3(NCHK, BHX), 256>>>();
        prefix_kernel<<<BHX, 256>>>();
        ssd_out_kernel<<<dim3(NCHK, BHX), QC>>>(Dparam + l * NHX);
        gatednorm_kernel<<<BT / 8, 256>>>(gnorm_w + l * DINNERX);
        mma_gemm<2><<<dim3(DMX / 64, BT / 128), 256, SM_TOTAL>>>(
            pYNhi, pYNlo,
            pW3hi + (size_t)l * DMX * DINNERX, pW3lo + (size_t)l * DMX * DINNERX,
            nullptr, pH, DMX, DINNERX);
    }

    zero_pool_kernel<<<4, 256>>>();
    pool_kernel<<<dim3(32, BB), DMX>>>(normf_w);
    final_kernel<<<BB, DIMX>>>(out_w, out_b, (float*)d_out);
}

// round 6
// speedup vs baseline: 1.3774x; 1.1580x over previous
#include <cuda_runtime.h>
#include <cuda_bf16.h>
#include <math.h>
#include <stdint.h>

#define BB 8
#define TT 2048
#define DIMX 512
#define DMX 128
#define DINNERX 256
#define NSTATEX 16
#define HDIMX 64
#define NHX 4
#define CONVD 288
#define PROJD 548
#define PROJPAD 576
#define LNUM 2
#define BT (BB*TT)          // 16384
#define QC 128              // chunk length
#define NCHK (TT/QC)        // 16
#define BHX (BB*NHX)        // 32
#define EPSF 1e-5f

// ------------------------- scratch (static device memory) -------------------
__device__ float g_H[BT*DMX];
__device__ float g_PROJ[BT*PROJD];
__device__ float g_CONVX[BT*CONVD];
__device__ float g_DT[BHX*TT];
__device__ float g_CUM[BHX*TT];
__device__ float g_SLOC[BHX*NCHK*HDIMX*NSTATEX];
__device__ float g_Y[BT*DINNERX];
__device__ float g_POOLP[BB*32*DMX];

__device__ __nv_bfloat16 g_xhi[BT*DIMX],    g_xlo[BT*DIMX];
__device__ __nv_bfloat16 g_hnhi[BT*DMX],    g_hnlo[BT*DMX];
__device__ __nv_bfloat16 g_ynhi[BT*DINNERX],g_ynlo[BT*DINNERX];
__device__ __nv_bfloat16 g_w1hi[DMX*DIMX],  g_w1lo[DMX*DIMX];
__device__ __nv_bfloat16 g_w2hi[LNUM*PROJPAD*DMX], g_w2lo[LNUM*PROJPAD*DMX];
__device__ __nv_bfloat16 g_w3hi[LNUM*DMX*DINNERX], g_w3lo[LNUM*DMX*DINNERX];

// ------------------------------ PTX helpers ---------------------------------
__device__ __forceinline__ uint32_t smem_u32(const void* p) {
    uint32_t a;
    asm("{ .reg .u64 t; cvta.to.shared.u64 t, %1; cvt.u32.u64 %0, t; }" : "=r"(a) : "l"(p));
    return a;
}
__device__ __forceinline__ void ldsm_x4(uint32_t* r, uint32_t addr) {
    asm volatile("ldmatrix.sync.aligned.m8n8.x4.shared.b16 {%0,%1,%2,%3}, [%4];"
        : "=r"(r[0]), "=r"(r[1]), "=r"(r[2]), "=r"(r[3]) : "r"(addr));
}
__device__ __forceinline__ void mma16816(float* c, const uint32_t* a, const uint32_t* b) {
    asm volatile("mma.sync.aligned.m16n8k16.row.col.f32.bf16.bf16.f32 "
        "{%0,%1,%2,%3}, {%4,%5,%6,%7}, {%8,%9}, {%0,%1,%2,%3};"
        : "+f"(c[0]), "+f"(c[1]), "+f"(c[2]), "+f"(c[3])
        : "r"(a[0]), "r"(a[1]), "r"(a[2]), "r"(a[3]), "r"(b[0]), "r"(b[1]));
}
__device__ __forceinline__ void cp16(uint32_t saddr, const void* g) {
    asm volatile("cp.async.ca.shared.global [%0], [%1], 16;" :: "r"(saddr), "l"(g));
}
__device__ __forceinline__ void cp_commit() {
    asm volatile("cp.async.commit_group;" ::: "memory");
}
template<int N> __device__ __forceinline__ void cp_wait() {
    asm volatile("cp.async.wait_group %0;" :: "n"(N) : "memory");
}

// ------------------------------ HMMA GEMM ------------------------------------
#define LDSA 72
#define A_BYTES (128*LDSA*2)
#define B_BYTES (64*LDSA*2)
#define OFF_ALO A_BYTES
#define OFF_BHI (2*A_BYTES)
#define OFF_BLO (2*A_BYTES + B_BYTES)
#define STAGE_BYTES (2*A_BYTES + 2*B_BYTES)
#define SM_TOTAL (2*STAGE_BYTES)

template<int MODE>
__global__ __launch_bounds__(256, 2) void mma_gemm(
    const __nv_bfloat16* __restrict__ Ahi, const __nv_bfloat16* __restrict__ Alo,
    const __nv_bfloat16* __restrict__ Whi, const __nv_bfloat16* __restrict__ Wlo,
    const float* __restrict__ bias, float* __restrict__ C,
    int N, int K)
{
    extern __shared__ char smem[];
    uint32_t sb = smem_u32(smem);
    int tid = threadIdx.x, wid = tid >> 5, lane = tid & 31;
    int m0 = blockIdx.y * 128, n0 = blockIdx.x * 64;
    int wm = (wid & 3) * 32, wn = (wid >> 2) * 32;

    float acc[2][4][4];
#pragma unroll
    for (int i = 0; i < 2; i++)
#pragma unroll
        for (int j = 0; j < 4; j++)
#pragma unroll
            for (int q = 0; q < 4; q++) acc[i][j][q] = 0.f;

    // A ldmatrix addresses (x4 over 16x16 tile)
    int lr = lane & 15;
    uint32_t aOff[2];
#pragma unroll
    for (int mt = 0; mt < 2; mt++)
        aOff[mt] = (uint32_t)((wm + mt * 16 + lr) * (LDSA * 2) + (lane >> 4) * 16);
    // B ldmatrix addresses: one x4 covers an nt-pair (2 n-tiles x 2 k-halves)
    uint32_t bOff[2];
    {
        int q = lane >> 3, rr = lane & 7;
#pragma unroll
        for (int p = 0; p < 2; p++) {
            int row = wn + p * 16 + (q >> 1) * 8 + rr;
            bOff[p] = (uint32_t)(OFF_BHI + row * (LDSA * 2) + (q & 1) * 16);
        }
    }

    int nstage = K >> 6;
    auto load_stage = [&](int buf, int k0) {
        uint32_t base = sb + buf * STAGE_BYTES;
#pragma unroll
        for (int i = 0; i < 4; i++) {
            int li = tid + i * 256;
            int r = li >> 3, g8 = li & 7;
            uint32_t so = (uint32_t)(r * (LDSA * 2) + g8 * 16);
            size_t goff = (size_t)(m0 + r) * K + k0 + g8 * 8;
            cp16(base + so, Ahi + goff);
            cp16(base + OFF_ALO + so, Alo + goff);
        }
#pragma unroll
        for (int i = 0; i < 2; i++) {
            int li = tid + i * 256;
            int r = li >> 3, g8 = li & 7;
            uint32_t so = (uint32_t)(r * (LDSA * 2) + g8 * 16);
            size_t goff = (size_t)(n0 + r) * K + k0 + g8 * 8;
            cp16(base + OFF_BHI + so, Whi + goff);
            cp16(base + OFF_BLO + so, Wlo + goff);
        }
    };

    load_stage(0, 0);
    cp_commit();

    for (int s = 0; s < nstage; s++) {
        if (s + 1 < nstage) load_stage((s + 1) & 1, (s + 1) * 64);
        cp_commit();
        if (s + 1 < nstage) cp_wait<1>(); else cp_wait<0>();
        __syncthreads();

        uint32_t sbuf = sb + (s & 1) * STAGE_BYTES;
#pragma unroll
        for (int ks = 0; ks < 64; ks += 16) {
            uint32_t kb = (uint32_t)(ks * 2);
            uint32_t ah[2][4], al[2][4], b4h[2][4], b4l[2][4];
#pragma unroll
            for (int mt = 0; mt < 2; mt++) {
                ldsm_x4(ah[mt], sbuf + aOff[mt] + kb);
                ldsm_x4(al[mt], sbuf + OFF_ALO + aOff[mt] + kb);
            }
#pragma unroll
            for (int p = 0; p < 2; p++) {
                ldsm_x4(b4h[p], sbuf + bOff[p] + kb);
                ldsm_x4(b4l[p], sbuf + bOff[p] + B_BYTES + kb);
            }
#pragma unroll
            for (int mt = 0; mt < 2; mt++)
#pragma unroll
                for (int p = 0; p < 2; p++)
#pragma unroll
                    for (int u = 0; u < 2; u++) {
                        int nt = 2 * p + u;
                        mma16816(acc[mt][nt], ah[mt], &b4h[p][u * 2]);
                        mma16816(acc[mt][nt], ah[mt], &b4l[p][u * 2]);
                        mma16816(acc[mt][nt], al[mt], &b4h[p][u * 2]);
                    }
        }
        __syncthreads();
    }

    // epilogue via smem for coalesced stores
    float* S = (float*)smem;          // [128][68]
    const int SW = 68;
    int crow = lane >> 2, ccol = (lane & 3) * 2;
#pragma unroll
    for (int mt = 0; mt < 2; mt++)
#pragma unroll
        for (int nt = 0; nt < 4; nt++) {
            int r = wm + mt * 16 + crow;
            int cc = wn + nt * 8 + ccol;
            S[r * SW + cc]           = acc[mt][nt][0];
            S[r * SW + cc + 1]       = acc[mt][nt][1];
            S[(r + 8) * SW + cc]     = acc[mt][nt][2];
            S[(r + 8) * SW + cc + 1] = acc[mt][nt][3];
        }
    __syncthreads();
#pragma unroll
    for (int it = 0; it < 32; it++) {
        int li = tid + it * 256;
        int cc = li & 63, r = li >> 6;
        int col = n0 + cc;
        if (col < N) {
            float v = S[r * SW + cc];
            if (MODE == 0) v += bias[col];
            size_t o = (size_t)(m0 + r) * N + col;
            if (MODE == 2) v += C[o];
            C[o] = v;
        }
    }
}

// --------------------------- bf16 split helpers ------------------------------
__device__ __forceinline__ void split1(float v, __nv_bfloat16& h, __nv_bfloat16& l) {
    h = __float2bfloat16_rn(v);
    l = __float2bfloat16_rn(v - __bfloat162float(h));
}

__global__ void split_kernel(const float* __restrict__ src,
                             __nv_bfloat16* __restrict__ hi,
                             __nv_bfloat16* __restrict__ lo, int n4)
{
    int i = blockIdx.x * blockDim.x + threadIdx.x;
    if (i >= n4) return;
    float4 v = ((const float4*)src)[i];
    __nv_bfloat16 h[4], l[4];
    split1(v.x, h[0], l[0]); split1(v.y, h[1], l[1]);
    split1(v.z, h[2], l[2]); split1(v.w, h[3], l[3]);
    *(uint2*)(hi + (size_t)i * 4) = *(uint2*)h;
    *(uint2*)(lo + (size_t)i * 4) = *(uint2*)l;
}

// all weight transposes+splits in ONE kernel
#define TS_R1 (DMX*DIMX)
#define TS_R2 (LNUM*PROJPAD*DMX)
#define TS_R3 (LNUM*DMX*DINNERX)
__global__ void tsplit_all(const float* __restrict__ in_w,
                           const float* __restrict__ inproj_w,
                           const float* __restrict__ outproj_w)
{
    int idx = blockIdx.x * blockDim.x + threadIdx.x;
    if (idx < TS_R1) {
        int n = idx / DIMX, k = idx % DIMX;
        float v = in_w[(size_t)k * DMX + n];
        split1(v, g_w1hi[idx], g_w1lo[idx]);
        return;
    }
    idx -= TS_R1;
    if (idx < TS_R2) {
        int l = idx / (PROJPAD * DMX), r = idx % (PROJPAD * DMX);
        int n = r / DMX, k = r % DMX;
        float v = (n < PROJD) ? inproj_w[(size_t)l * DMX * PROJD + (size_t)k * PROJD + n] : 0.f;
        split1(v, g_w2hi[idx], g_w2lo[idx]);
        return;
    }
    idx -= TS_R2;
    if (idx < TS_R3) {
        int l = idx / (DMX * DINNERX), r = idx % (DMX * DINNERX);
        int n = r / DINNERX, k = r % DINNERX;
        float v = outproj_w[(size_t)l * DINNERX * DMX + (size_t)k * DMX + n];
        split1(v, g_w3hi[idx], g_w3lo[idx]);
    }
}

// ------------------------------ rmsnorm (DM=128) -----------------------------
__global__ void rmsnorm128_kernel(const float* __restrict__ src,
                                  const float* __restrict__ w,
                                  __nv_bfloat16* __restrict__ hi,
                                  __nv_bfloat16* __restrict__ lo)
{
    int warp = (blockIdx.x * blockDim.x + threadIdx.x) >> 5;
    int lane = threadIdx.x & 31;
    if (warp >= BT) return;
    const float* row = src + (size_t)warp * DMX;
    float4 v = *(const float4*)(row + lane * 4);
    float ss = v.x*v.x + v.y*v.y + v.z*v.z + v.w*v.w;
#pragma unroll
    for (int o = 16; o; o >>= 1) ss += __shfl_xor_sync(0xffffffffu, ss, o);
    float r = rsqrtf(ss * (1.f / DMX) + EPSF);
    float4 wv = *(const float4*)(w + lane * 4);
    float ov[4] = { v.x*r*wv.x, v.y*r*wv.y, v.z*r*wv.z, v.w*r*wv.w };
    size_t base = (size_t)warp * DMX + lane * 4;
    __nv_bfloat16 h[4], l[4];
#pragma unroll
    for (int j = 0; j < 4; j++) split1(ov[j], h[j], l[j]);
    *(uint2*)(hi + base) = *(uint2*)h;
    *(uint2*)(lo + base) = *(uint2*)l;
}

// ------------------------ causal conv + silu (prefetch 8) --------------------
__global__ __launch_bounds__(288) void conv_kernel(const float* __restrict__ cw,
                                                   const float* __restrict__ cb)
{
    int b = blockIdx.y;
    int t0 = blockIdx.x * 64;
    int c = threadIdx.x;
    float w0 = cw[c*4], w1 = cw[c*4+1], w2 = cw[c*4+2], w3 = cw[c*4+3];
    float bias = cb[c];
    size_t base = (size_t)(b * TT) * PROJD + DINNERX + c;
    float xm3 = 0.f, xm2 = 0.f, xm1 = 0.f;
    if (t0 >= 3) {
        xm3 = g_PROJ[base + (size_t)(t0-3) * PROJD];
        xm2 = g_PROJ[base + (size_t)(t0-2) * PROJD];
        xm1 = g_PROJ[base + (size_t)(t0-1) * PROJD];
    }
    for (int i = 0; i < 8; i++) {
        float xv[8];
#pragma unroll
        for (int j = 0; j < 8; j++)
            xv[j] = g_PROJ[base + (size_t)(t0 + i*8 + j) * PROJD];
#pragma unroll
        for (int j = 0; j < 8; j++) {
            float a = bias + w0*xm3 + w1*xm2 + w2*xm1 + w3*xv[j];
            g_CONVX[(size_t)(b * TT + t0 + i*8 + j) * CONVD + c] = a / (1.f + __expf(-a));
            xm3 = xm2; xm2 = xm1; xm1 = xv[j];
        }
    }
}

// ---------------- chunkstate (fused softplus + cumsum + local state) ---------
__global__ __launch_bounds__(256) void chunkstate_kernel(const float* __restrict__ Alog,
                                                         const float* __restrict__ dtb)
{
    int c = blockIdx.x, bh = blockIdx.y;
    int b = bh >> 2, h = bh & 3;
    int tid = threadIdx.x;
    __shared__ float sc[QC];
    __shared__ float sdt[QC];
    __shared__ float coef[QC];
    __shared__ float Xs[16][HDIMX];
    __shared__ float Bsh[16][NSTATEX];
    int cbase = bh * TT + c * QC;
    size_t rowbase = (size_t)(b * TT + c * QC);

    float Ah = -__expf(Alog[h]);
    if (tid < QC) {
        float v = g_PROJ[(size_t)(b * TT + c * QC + tid) * PROJD + DINNERX + CONVD + h] + dtb[h];
        float sp = (v > 20.f) ? v : log1pf(__expf(v));
        sdt[tid] = sp;
        sc[tid] = sp * Ah;
    }
    __syncthreads();
#pragma unroll
    for (int off = 1; off < QC; off <<= 1) {
        float x = 0.f;
        if (tid < QC && tid >= off) x = sc[tid - off];
        __syncthreads();
        if (tid < QC) sc[tid] += x;
        __syncthreads();
    }
    if (tid < QC) {
        g_DT[cbase + tid]  = sdt[tid];
        g_CUM[cbase + tid] = sc[tid];
        coef[tid] = __expf(sc[QC - 1] - sc[tid]) * sdt[tid];
    }

    float acc[4] = {0.f, 0.f, 0.f, 0.f};
    int p = tid >> 2, ng = (tid & 3) * 4;
    for (int tt = 0; tt < QC; tt += 16) {
        __syncthreads();
#pragma unroll
        for (int j = 0; j < 4; j++) {
            int li = tid + j * 256;
            int r = li >> 6, pp = li & 63;
            Xs[r][pp] = g_CONVX[(rowbase + tt + r) * CONVD + h * 64 + pp];
        }
        {
            int r = tid >> 4, n = tid & 15;
            Bsh[r][n] = g_CONVX[(rowbase + tt + r) * CONVD + 256 + n];
        }
        __syncthreads();
#pragma unroll
        for (int r = 0; r < 16; r++) {
            float cx = coef[tt + r] * Xs[r][p];
#pragma unroll
            for (int j = 0; j < 4; j++) acc[j] += cx * Bsh[r][ng + j];
        }
    }
    size_t dst = ((size_t)bh * NCHK + c) * (HDIMX * NSTATEX) + p * NSTATEX + ng;
    *(float4*)(g_SLOC + dst) = make_float4(acc[0], acc[1], acc[2], acc[3]);
}

// ------------------------------ SSD output (fused prefix) --------------------
__global__ __launch_bounds__(128) void ssd_out_kernel(const float* __restrict__ Dp)
{
    int c = blockIdx.x, bh = blockIdx.y;
    int b = bh >> 2, h = bh & 3;
    int t = threadIdx.x;
    __shared__ float4 sX[QC][16];
    __shared__ float4 sB4[QC][4];
    __shared__ float4 sSin[HDIMX][4];
    __shared__ float sCum[QC];
    __shared__ float sDt[QC];
    size_t rowbase = (size_t)(b * TT + c * QC);
    int cbase = bh * TT + c * QC;

#pragma unroll
    for (int j = 0; j < 16; j++) {
        int li = t + j * 128;
        int r = li >> 4, p4 = li & 15;
        sX[r][p4] = *(const float4*)(g_CONVX + (rowbase + r) * CONVD + h * 64 + p4 * 4);
    }
#pragma unroll
    for (int j = 0; j < 4; j++) {
        int li = t + j * 128;
        int r = li >> 2, n4 = li & 3;
        sB4[r][n4] = *(const float4*)(g_CONVX + (rowbase + r) * CONVD + 256 + n4 * 4);
    }
    // in-block prefix over earlier chunks: Sin = sum_{j<c} SLOC_j * prod dec
    {
        size_t sbase = (size_t)bh * NCHK * (HDIMX * NSTATEX);
        int i0 = t * 8;
        float4 s0 = make_float4(0.f,0.f,0.f,0.f), s1 = s0;
        for (int j = 0; j < c; j++) {
            float dj = __expf(g_CUM[bh * TT + j * QC + QC - 1]);
            float4 a0 = *(const float4*)(g_SLOC + sbase + j * (HDIMX*NSTATEX) + i0);
            float4 a1 = *(const float4*)(g_SLOC + sbase + j * (HDIMX*NSTATEX) + i0 + 4);
            s0.x = s0.x*dj + a0.x; s0.y = s0.y*dj + a0.y;
            s0.z = s0.z*dj + a0.z; s0.w = s0.w*dj + a0.w;
            s1.x = s1.x*dj + a1.x; s1.y = s1.y*dj + a1.y;
            s1.z = s1.z*dj + a1.z; s1.w = s1.w*dj + a1.w;
        }
        sSin[t >> 1][(t & 1) * 2]     = s0;
        sSin[t >> 1][(t & 1) * 2 + 1] = s1;
    }
    sCum[t] = g_CUM[cbase + t];
    sDt[t]  = g_DT[cbase + t];
    float4 c4[4];
#pragma unroll
    for (int n4 = 0; n4 < 4; n4++)
        c4[n4] = *(const float4*)(g_CONVX + (rowbase + t) * CONVD + 272 + n4 * 4);
    __syncthreads();

    float ct  = sCum[t];
    float ect = __expf(ct);
    float Dh  = Dp[h];
    float4 y4[16];
#pragma unroll
    for (int p4 = 0; p4 < 16; p4++) {
        float a0 = 0.f, a1 = 0.f, a2 = 0.f, a3 = 0.f;
#pragma unroll
        for (int n4 = 0; n4 < 4; n4++) {
            float4 cc = c4[n4];
            float4 s0 = sSin[p4*4+0][n4], s1 = sSin[p4*4+1][n4];
            float4 s2 = sSin[p4*4+2][n4], s3 = sSin[p4*4+3][n4];
            a0 += cc.x*s0.x + cc.y*s0.y + cc.z*s0.z + cc.w*s0.w;
            a1 += cc.x*s1.x + cc.y*s1.y + cc.z*s1.z + cc.w*s1.w;
            a2 += cc.x*s2.x + cc.y*s2.y + cc.z*s2.z + cc.w*s2.w;
            a3 += cc.x*s3.x + cc.y*s3.y + cc.z*s3.z + cc.w*s3.w;
        }
        float4 xv = sX[t][p4];
        y4[p4].x = ect * a0 + Dh * xv.x;
        y4[p4].y = ect * a1 + Dh * xv.y;
        y4[p4].z = ect * a2 + Dh * xv.z;
        y4[p4].w = ect * a3 + Dh * xv.w;
    }

    int smax = t | 31;
    for (int s = 0; s <= smax; s++) {
        if (s <= t) {
            float d = 0.f;
#pragma unroll
            for (int n4 = 0; n4 < 4; n4++) {
                float4 cc = c4[n4], bb = sB4[s][n4];
                d += cc.x*bb.x + cc.y*bb.y + cc.z*bb.z + cc.w*bb.w;
            }
            float g = __expf(ct - sCum[s]) * sDt[s] * d;
#pragma unroll
            for (int p4 = 0; p4 < 16; p4++) {
                float4 xv = sX[s][p4];
                y4[p4].x += g * xv.x; y4[p4].y += g * xv.y;
                y4[p4].z += g * xv.z; y4[p4].w += g * xv.w;
            }
        }
    }

    __syncthreads();
#pragma unroll
    for (int p4 = 0; p4 < 16; p4++) sX[t][p4] = y4[p4];
    __syncthreads();
#pragma unroll
    for (int j = 0; j < 16; j++) {
        int li = t + j * 128;
        int r = li >> 4, p4 = li & 15;
        *(float4*)(g_Y + (rowbase + r) * DINNERX + h * 64 + p4 * 4) = sX[r][p4];
    }
}

// --------------------------- gated rmsnorm (float4) --------------------------
__global__ void gatednorm_kernel(const float* __restrict__ gnw)
{
    int warp = (blockIdx.x * blockDim.x + threadIdx.x) >> 5;
    int lane = threadIdx.x & 31;
    if (warp >= BT) return;
    const float4* yr = (const float4*)(g_Y + (size_t)warp * DINNERX);
    const float4* gr = (const float4*)(g_PROJ + (size_t)warp * PROJD);
    float v[8];
    float ss = 0.f;
#pragma unroll
    for (int q = 0; q < 2; q++) {
        float4 yv = yr[lane * 2 + q];
        float4 gv = gr[lane * 2 + q];
        float* vv = v + q * 4;
        float gy[4] = { gv.x, gv.y, gv.z, gv.w };
        float yy[4] = { yv.x, yv.y, yv.z, yv.w };
#pragma unroll
        for (int i = 0; i < 4; i++) {
            float s = gy[i] / (1.f + __expf(-gy[i]));
            float t = yy[i] * s;
            vv[i] = t;
            ss += t * t;
        }
    }
#pragma unroll
    for (int o = 16; o; o >>= 1) ss += __shfl_xor_sync(0xffffffffu, ss, o);
    float r = rsqrtf(ss * (1.f / DINNERX) + EPSF);
    size_t base = (size_t)warp * DINNERX + lane * 8;
    __nv_bfloat16 h[8], l[8];
#pragma unroll
    for (int i = 0; i < 8; i++) split1(v[i] * r * gnw[lane * 8 + i], h[i], l[i]);
    *(uint4*)(g_ynhi + base) = *(uint4*)h;
    *(uint4*)(g_ynlo + base) = *(uint4*)l;
}

// ---------------------------- final pool + head ------------------------------
__global__ __launch_bounds__(128) void pool_kernel(const float* __restrict__ nfw)
{
    int b = blockIdx.y;
    int chunk = blockIdx.x;
    int d = threadIdx.x;
    __shared__ float wsum[4];
    float wnf = nfw[d];
    float acc = 0.f;
    for (int r = 0; r < 64; r++) {
        int t = chunk * 64 + r;
        float v = g_H[(size_t)(b * TT + t) * DMX + d];
        float ss = v * v;
#pragma unroll
        for (int o = 16; o; o >>= 1) ss += __shfl_xor_sync(0xffffffffu, ss, o);
        if ((d & 31) == 0) wsum[d >> 5] = ss;
        __syncthreads();
        float tot = wsum[0] + wsum[1] + wsum[2] + wsum[3];
        __syncthreads();
        acc += v * rsqrtf(tot * (1.f / DMX) + EPSF) * wnf;
    }
    g_POOLP[(size_t)(b * 32 + chunk) * DMX + d] = acc * (1.f / TT);
}

__global__ void final_kernel(const float* __restrict__ ow,
                             const float* __restrict__ ob,
                             float* __restrict__ out)
{
    int b = blockIdx.x;
    int j = threadIdx.x;
    __shared__ float p[DMX];
    if (j < DMX) {
        float s = 0.f;
#pragma unroll 8
        for (int k = 0; k < 32; k++) s += g_POOLP[(size_t)(b * 32 + k) * DMX + j];
        p[j] = s;
    }
    __syncthreads();
    float acc = ob[j];
#pragma unroll 4
    for (int k = 0; k < DMX; k++) acc += p[k] * ow[k * DIMX + j];
    out[b * DIMX + j] = acc;
}

// ------------------------------ launcher -------------------------------------
extern "C" void kernel_launch(void* const* d_in, const int* in_sizes, int n_in,
                              void* d_out, int out_size)
{
    const float* x         = (const float*)d_in[0];
    const float* in_w      = (const float*)d_in[1];
    const float* in_b      = (const float*)d_in[2];
    const float* norm_w    = (const float*)d_in[3];
    const float* inproj_w  = (const float*)d_in[4];
    const float* conv_w    = (const float*)d_in[5];
    const float* conv_b    = (const float*)d_in[6];
    const float* A_log     = (const float*)d_in[7];
    const float* Dparam    = (const float*)d_in[8];
    const float* dt_bias   = (const float*)d_in[9];
    const float* gnorm_w   = (const float*)d_in[10];
    const float* outproj_w = (const float*)d_in[11];
    const float* normf_w   = (const float*)d_in[12];
    const float* out_w     = (const float*)d_in[13];
    const float* out_b     = (const float*)d_in[14];

    float *pH, *pPROJ;
    __nv_bfloat16 *pXhi, *pXlo, *pHNhi, *pHNlo, *pYNhi, *pYNlo;
    __nv_bfloat16 *pW1hi, *pW1lo, *pW2hi, *pW2lo, *pW3hi, *pW3lo;
    cudaGetSymbolAddress((void**)&pH,    g_H);
    cudaGetSymbolAddress((void**)&pPROJ, g_PROJ);
    cudaGetSymbolAddress((void**)&pXhi,  g_xhi);
    cudaGetSymbolAddress((void**)&pXlo,  g_xlo);
    cudaGetSymbolAddress((void**)&pHNhi, g_hnhi);
    cudaGetSymbolAddress((void**)&pHNlo, g_hnlo);
    cudaGetSymbolAddress((void**)&pYNhi, g_ynhi);
    cudaGetSymbolAddress((void**)&pYNlo, g_ynlo);
    cudaGetSymbolAddress((void**)&pW1hi, g_w1hi);
    cudaGetSymbolAddress((void**)&pW1lo, g_w1lo);
    cudaGetSymbolAddress((void**)&pW2hi, g_w2hi);
    cudaGetSymbolAddress((void**)&pW2lo, g_w2lo);
    cudaGetSymbolAddress((void**)&pW3hi, g_w3hi);
    cudaGetSymbolAddress((void**)&pW3lo, g_w3lo);

    cudaFuncSetAttribute(mma_gemm<0>, cudaFuncAttributeMaxDynamicSharedMemorySize, SM_TOTAL);
    cudaFuncSetAttribute(mma_gemm<1>, cudaFuncAttributeMaxDynamicSharedMemorySize, SM_TOTAL);
    cudaFuncSetAttribute(mma_gemm<2>, cudaFuncAttributeMaxDynamicSharedMemorySize, SM_TOTAL);

    // 0: x split (float4)
    split_kernel<<<(BT * DIMX / 4 + 255) / 256, 256>>>(x, pXhi, pXlo, BT * DIMX / 4);
    // 1: all weight transposes+splits
    tsplit_all<<<(TS_R1 + TS_R2 + TS_R3 + 255) / 256, 256>>>(in_w, inproj_w, outproj_w);
    // 2: h = x @ in_w + in_b
    mma_gemm<0><<<dim3(DMX / 64, BT / 128), 256, SM_TOTAL>>>(
        pXhi, pXlo, pW1hi, pW1lo, in_b, pH, DMX, DIMX);

    for (int l = 0; l < LNUM; l++) {
        rmsnorm128_kernel<<<BT / 8, 256>>>(pH, norm_w + l * DMX, pHNhi, pHNlo);
        mma_gemm<1><<<dim3(PROJPAD / 64, BT / 128), 256, SM_TOTAL>>>(
            pHNhi, pHNlo,
            pW2hi + (size_t)l * PROJPAD * DMX, pW2lo + (size_t)l * PROJPAD * DMX,
            nullptr, pPROJ, PROJD, DMX);
        conv_kernel<<<dim3(TT / 64, BB), 288>>>(
            conv_w + l * CONVD * 4, conv_b + l * CONVD);
        chunkstate_kernel<<<dim3(NCHK, BHX), 256>>>(A_log + l * NHX, dt_bias + l * NHX);
        ssd_out_kernel<<<dim3(NCHK, BHX), QC>>>(Dparam + l * NHX);
        gatednorm_kernel<<<BT / 8, 256>>>(gnorm_w + l * DINNERX);
        mma_gemm<2><<<dim3(DMX / 64, BT / 128), 256, SM_TOTAL>>>(
            pYNhi, pYNlo,
            pW3hi + (size_t)l * DMX * DINNERX, pW3lo + (size_t)l * DMX * DINNERX,
            nullptr, pH, DMX, DINNERX);
    }

    pool_kernel<<<dim3(32, BB), DMX>>>(normf_w);
    final_kernel<<<BB, DIMX>>>(out_w, out_b, (float*)d_out);
}

// round 7
// speedup vs baseline: 1.4937x; 1.0844x over previous
#include <cuda_runtime.h>
#include <cuda_fp16.h>
#include <math.h>
#include <stdint.h>

#define BB 8
#define TT 2048
#define DIMX 512
#define DMX 128
#define DINNERX 256
#define NSTATEX 16
#define HDIMX 64
#define NHX 4
#define CONVD 288
#define PROJD 548
#define PROJPAD 576
#define LNUM 2
#define BT (BB*TT)          // 16384
#define QC 128              // chunk length
#define NCHK (TT/QC)        // 16
#define BHX (BB*NHX)        // 32
#define EPSF 1e-5f

// ------------------------- scratch (static device memory) -------------------
__device__ float g_H[BT*DMX];
__device__ float g_PROJ[BT*PROJD];
__device__ float g_CONVX[BT*CONVD];
__device__ float g_DT[BHX*TT];
__device__ float g_CUM[BHX*TT];
__device__ float g_SLOC[BHX*NCHK*HDIMX*NSTATEX];
__device__ float g_Y[BT*DINNERX];
__device__ float g_POOLP[BB*32*DMX];

// fp16 activations (single) / fp16 hi+lo weights
__device__ __half g_xh[BT*DIMX];
__device__ __half g_hnh[BT*DMX];
__device__ __half g_ynh[BT*DINNERX];
__device__ __half g_w1hi[DMX*DIMX],  g_w1lo[DMX*DIMX];
__device__ __half g_w2hi[LNUM*PROJPAD*DMX], g_w2lo[LNUM*PROJPAD*DMX];
__device__ __half g_w3hi[LNUM*DMX*DINNERX], g_w3lo[LNUM*DMX*DINNERX];

// ------------------------------ PTX helpers ---------------------------------
__device__ __forceinline__ uint32_t smem_u32(const void* p) {
    uint32_t a;
    asm("{ .reg .u64 t; cvta.to.shared.u64 t, %1; cvt.u32.u64 %0, t; }" : "=r"(a) : "l"(p));
    return a;
}
__device__ __forceinline__ void ldsm_x4(uint32_t* r, uint32_t addr) {
    asm volatile("ldmatrix.sync.aligned.m8n8.x4.shared.b16 {%0,%1,%2,%3}, [%4];"
        : "=r"(r[0]), "=r"(r[1]), "=r"(r[2]), "=r"(r[3]) : "r"(addr));
}
__device__ __forceinline__ void mma16816(float* c, const uint32_t* a, const uint32_t* b) {
    asm volatile("mma.sync.aligned.m16n8k16.row.col.f32.f16.f16.f32 "
        "{%0,%1,%2,%3}, {%4,%5,%6,%7}, {%8,%9}, {%0,%1,%2,%3};"
        : "+f"(c[0]), "+f"(c[1]), "+f"(c[2]), "+f"(c[3])
        : "r"(a[0]), "r"(a[1]), "r"(a[2]), "r"(a[3]), "r"(b[0]), "r"(b[1]));
}
__device__ __forceinline__ void cp16(uint32_t saddr, const void* g) {
    asm volatile("cp.async.ca.shared.global [%0], [%1], 16;" :: "r"(saddr), "l"(g));
}
__device__ __forceinline__ void cp_commit() {
    asm volatile("cp.async.commit_group;" ::: "memory");
}
template<int N> __device__ __forceinline__ void cp_wait() {
    asm volatile("cp.async.wait_group %0;" :: "n"(N) : "memory");
}

// ------------------------------ HMMA GEMM ------------------------------------
// C[M,N] = A[M,K] @ W[K,N];  A fp16 [M][K];  W as Wt fp16 hi/lo [Npad][K].
// 2-term: D = A*Whi + A*Wlo. Block 128x64, 8 warps 32x32, K staged 64, 2-buf.
#define LDSA 72
#define A_BYTES (128*LDSA*2)                 // 18432
#define B_BYTES (64*LDSA*2)                  // 9216
#define OFF_BHI A_BYTES
#define OFF_BLO (A_BYTES + B_BYTES)
#define STAGE_BYTES (A_BYTES + 2*B_BYTES)    // 36864
#define SM_TOTAL (2*STAGE_BYTES)             // 73728

template<int MODE>   // 0: C=D+bias ; 1: C=D ; 2: C+=D
__global__ __launch_bounds__(256, 2) void mma_gemm(
    const __half* __restrict__ A,
    const __half* __restrict__ Whi, const __half* __restrict__ Wlo,
    const float* __restrict__ bias, float* __restrict__ C,
    int N, int K)
{
    extern __shared__ char smem[];
    uint32_t sb = smem_u32(smem);
    int tid = threadIdx.x, wid = tid >> 5, lane = tid & 31;
    int m0 = blockIdx.y * 128, n0 = blockIdx.x * 64;
    int wm = (wid & 3) * 32, wn = (wid >> 2) * 32;

    float acc[2][4][4];
#pragma unroll
    for (int i = 0; i < 2; i++)
#pragma unroll
        for (int j = 0; j < 4; j++)
#pragma unroll
            for (int q = 0; q < 4; q++) acc[i][j][q] = 0.f;

    int lr = lane & 15;
    uint32_t aOff[2];
#pragma unroll
    for (int mt = 0; mt < 2; mt++)
        aOff[mt] = (uint32_t)((wm + mt * 16 + lr) * (LDSA * 2) + (lane >> 4) * 16);
    uint32_t bOff[2];
    {
        int q = lane >> 3, rr = lane & 7;
#pragma unroll
        for (int p = 0; p < 2; p++) {
            int row = wn + p * 16 + (q >> 1) * 8 + rr;
            bOff[p] = (uint32_t)(OFF_BHI + row * (LDSA * 2) + (q & 1) * 16);
        }
    }

    int nstage = K >> 6;
    auto load_stage = [&](int buf, int k0) {
        uint32_t base = sb + buf * STAGE_BYTES;
#pragma unroll
        for (int i = 0; i < 4; i++) {
            int li = tid + i * 256;               // 1024 chunks for A
            int r = li >> 3, g8 = li & 7;
            uint32_t so = (uint32_t)(r * (LDSA * 2) + g8 * 16);
            size_t goff = (size_t)(m0 + r) * K + k0 + g8 * 8;
            cp16(base + so, A + goff);
        }
#pragma unroll
        for (int i = 0; i < 2; i++) {
            int li = tid + i * 256;               // 512 chunks per B operand
            int r = li >> 3, g8 = li & 7;
            uint32_t so = (uint32_t)(r * (LDSA * 2) + g8 * 16);
            size_t goff = (size_t)(n0 + r) * K + k0 + g8 * 8;
            cp16(base + OFF_BHI + so, Whi + goff);
            cp16(base + OFF_BLO + so, Wlo + goff);
        }
    };

    load_stage(0, 0);
    cp_commit();

    for (int s = 0; s < nstage; s++) {
        if (s + 1 < nstage) load_stage((s + 1) & 1, (s + 1) * 64);
        cp_commit();
        if (s + 1 < nstage) cp_wait<1>(); else cp_wait<0>();
        __syncthreads();

        uint32_t sbuf = sb + (s & 1) * STAGE_BYTES;
#pragma unroll
        for (int ks = 0; ks < 64; ks += 16) {
            uint32_t kb = (uint32_t)(ks * 2);
            uint32_t ah[2][4], b4h[2][4], b4l[2][4];
#pragma unroll
            for (int mt = 0; mt < 2; mt++)
                ldsm_x4(ah[mt], sbuf + aOff[mt] + kb);
#pragma unroll
            for (int p = 0; p < 2; p++) {
                ldsm_x4(b4h[p], sbuf + bOff[p] + kb);
                ldsm_x4(b4l[p], sbuf + bOff[p] + B_BYTES + kb);
            }
#pragma unroll
            for (int mt = 0; mt < 2; mt++)
#pragma unroll
                for (int p = 0; p < 2; p++)
#pragma unroll
                    for (int u = 0; u < 2; u++) {
                        int nt = 2 * p + u;
                        mma16816(acc[mt][nt], ah[mt], &b4h[p][u * 2]);
                        mma16816(acc[mt][nt], ah[mt], &b4l[p][u * 2]);
                    }
        }
        __syncthreads();
    }

    // epilogue via smem for coalesced stores
    float* S = (float*)smem;          // [128][68] = 34816 B
    const int SW = 68;
    int crow = lane >> 2, ccol = (lane & 3) * 2;
#pragma unroll
    for (int mt = 0; mt < 2; mt++)
#pragma unroll
        for (int nt = 0; nt < 4; nt++) {
            int r = wm + mt * 16 + crow;
            int cc = wn + nt * 8 + ccol;
            S[r * SW + cc]           = acc[mt][nt][0];
            S[r * SW + cc + 1]       = acc[mt][nt][1];
            S[(r + 8) * SW + cc]     = acc[mt][nt][2];
            S[(r + 8) * SW + cc + 1] = acc[mt][nt][3];
        }
    __syncthreads();
#pragma unroll
    for (int it = 0; it < 32; it++) {
        int li = tid + it * 256;
        int cc = li & 63, r = li >> 6;
        int col = n0 + cc;
        if (col < N) {
            float v = S[r * SW + cc];
            if (MODE == 0) v += bias[col];
            size_t o = (size_t)(m0 + r) * N + col;
            if (MODE == 2) v += C[o];
            C[o] = v;
        }
    }
}

// --------------------------- fp16 split helpers ------------------------------
__device__ __forceinline__ void splith(float v, __half& h, __half& l) {
    h = __float2half_rn(v);
    l = __float2half_rn(v - __half2float(h));
}

__global__ void split_kernel(const float* __restrict__ src,
                             __half* __restrict__ dst, int n4)
{
    int i = blockIdx.x * blockDim.x + threadIdx.x;
    if (i >= n4) return;
    float4 v = ((const float4*)src)[i];
    __half h[4] = { __float2half_rn(v.x), __float2half_rn(v.y),
                    __float2half_rn(v.z), __float2half_rn(v.w) };
    *(uint2*)(dst + (size_t)i * 4) = *(uint2*)h;
}

// all weight transposes+splits in ONE kernel
#define TS_R1 (DMX*DIMX)
#define TS_R2 (LNUM*PROJPAD*DMX)
#define TS_R3 (LNUM*DMX*DINNERX)
__global__ void tsplit_all(const float* __restrict__ in_w,
                           const float* __restrict__ inproj_w,
                           const float* __restrict__ outproj_w)
{
    int idx = blockIdx.x * blockDim.x + threadIdx.x;
    if (idx < TS_R1) {
        int n = idx / DIMX, k = idx % DIMX;
        float v = in_w[(size_t)k * DMX + n];
        splith(v, g_w1hi[idx], g_w1lo[idx]);
        return;
    }
    idx -= TS_R1;
    if (idx < TS_R2) {
        int l = idx / (PROJPAD * DMX), r = idx % (PROJPAD * DMX);
        int n = r / DMX, k = r % DMX;
        float v = (n < PROJD) ? inproj_w[(size_t)l * DMX * PROJD + (size_t)k * PROJD + n] : 0.f;
        splith(v, g_w2hi[idx], g_w2lo[idx]);
        return;
    }
    idx -= TS_R2;
    if (idx < TS_R3) {
        int l = idx / (DMX * DINNERX), r = idx % (DMX * DINNERX);
        int n = r / DINNERX, k = r % DINNERX;
        float v = outproj_w[(size_t)l * DINNERX * DMX + (size_t)k * DMX + n];
        splith(v, g_w3hi[idx], g_w3lo[idx]);
    }
}

// ------------------------------ rmsnorm (DM=128) -----------------------------
__global__ void rmsnorm128_kernel(const float* __restrict__ src,
                                  const float* __restrict__ w,
                                  __half* __restrict__ dst)
{
    int warp = (blockIdx.x * blockDim.x + threadIdx.x) >> 5;
    int lane = threadIdx.x & 31;
    if (warp >= BT) return;
    const float* row = src + (size_t)warp * DMX;
    float4 v = *(const float4*)(row + lane * 4);
    float ss = v.x*v.x + v.y*v.y + v.z*v.z + v.w*v.w;
#pragma unroll
    for (int o = 16; o; o >>= 1) ss += __shfl_xor_sync(0xffffffffu, ss, o);
    float r = rsqrtf(ss * (1.f / DMX) + EPSF);
    float4 wv = *(const float4*)(w + lane * 4);
    __half h[4] = { __float2half_rn(v.x*r*wv.x), __float2half_rn(v.y*r*wv.y),
                    __float2half_rn(v.z*r*wv.z), __float2half_rn(v.w*r*wv.w) };
    *(uint2*)(dst + (size_t)warp * DMX + lane * 4) = *(uint2*)h;
}

// ------------------------ causal conv + silu (prefetch 8) --------------------
__global__ __launch_bounds__(288) void conv_kernel(const float* __restrict__ cw,
                                                   const float* __restrict__ cb)
{
    int b = blockIdx.y;
    int t0 = blockIdx.x * 64;
    int c = threadIdx.x;
    float w0 = cw[c*4], w1 = cw[c*4+1], w2 = cw[c*4+2], w3 = cw[c*4+3];
    float bias = cb[c];
    size_t base = (size_t)(b * TT) * PROJD + DINNERX + c;
    float xm3 = 0.f, xm2 = 0.f, xm1 = 0.f;
    if (t0 >= 3) {
        xm3 = g_PROJ[base + (size_t)(t0-3) * PROJD];
        xm2 = g_PROJ[base + (size_t)(t0-2) * PROJD];
        xm1 = g_PROJ[base + (size_t)(t0-1) * PROJD];
    }
    for (int i = 0; i < 8; i++) {
        float xv[8];
#pragma unroll
        for (int j = 0; j < 8; j++)
            xv[j] = g_PROJ[base + (size_t)(t0 + i*8 + j) * PROJD];
#pragma unroll
        for (int j = 0; j < 8; j++) {
            float a = bias + w0*xm3 + w1*xm2 + w2*xm1 + w3*xv[j];
            g_CONVX[(size_t)(b * TT + t0 + i*8 + j) * CONVD + c] = a / (1.f + __expf(-a));
            xm3 = xm2; xm2 = xm1; xm1 = xv[j];
        }
    }
}

// ---------------- chunkstate (fused softplus + cumsum + local state) ---------
__global__ __launch_bounds__(256) void chunkstate_kernel(const float* __restrict__ Alog,
                                                         const float* __restrict__ dtb)
{
    int c = blockIdx.x, bh = blockIdx.y;
    int b = bh >> 2, h = bh & 3;
    int tid = threadIdx.x;
    __shared__ float sc[QC];
    __shared__ float sdt[QC];
    __shared__ float coef[QC];
    __shared__ float Xs[16][HDIMX];
    __shared__ float Bsh[16][NSTATEX];
    int cbase = bh * TT + c * QC;
    size_t rowbase = (size_t)(b * TT + c * QC);

    float Ah = -__expf(Alog[h]);
    if (tid < QC) {
        float v = g_PROJ[(size_t)(b * TT + c * QC + tid) * PROJD + DINNERX + CONVD + h] + dtb[h];
        float sp = (v > 20.f) ? v : log1pf(__expf(v));
        sdt[tid] = sp;
        sc[tid] = sp * Ah;
    }
    __syncthreads();
#pragma unroll
    for (int off = 1; off < QC; off <<= 1) {
        float x = 0.f;
        if (tid < QC && tid >= off) x = sc[tid - off];
        __syncthreads();
        if (tid < QC) sc[tid] += x;
        __syncthreads();
    }
    if (tid < QC) {
        g_DT[cbase + tid]  = sdt[tid];
        g_CUM[cbase + tid] = sc[tid];
        coef[tid] = __expf(sc[QC - 1] - sc[tid]) * sdt[tid];
    }

    float acc[4] = {0.f, 0.f, 0.f, 0.f};
    int p = tid >> 2, ng = (tid & 3) * 4;
    for (int tt = 0; tt < QC; tt += 16) {
        __syncthreads();
#pragma unroll
        for (int j = 0; j < 4; j++) {
            int li = tid + j * 256;
            int r = li >> 6, pp = li & 63;
            Xs[r][pp] = g_CONVX[(rowbase + tt + r) * CONVD + h * 64 + pp];
        }
        {
            int r = tid >> 4, n = tid & 15;
            Bsh[r][n] = g_CONVX[(rowbase + tt + r) * CONVD + 256 + n];
        }
        __syncthreads();
#pragma unroll
        for (int r = 0; r < 16; r++) {
            float cx = coef[tt + r] * Xs[r][p];
#pragma unroll
            for (int j = 0; j < 4; j++) acc[j] += cx * Bsh[r][ng + j];
        }
    }
    size_t dst = ((size_t)bh * NCHK + c) * (HDIMX * NSTATEX) + p * NSTATEX + ng;
    *(float4*)(g_SLOC + dst) = make_float4(acc[0], acc[1], acc[2], acc[3]);
}

// ------------------------------ SSD output (fused prefix) --------------------
__global__ __launch_bounds__(128) void ssd_out_kernel(const float* __restrict__ Dp)
{
    int c = blockIdx.x, bh = blockIdx.y;
    int b = bh >> 2, h = bh & 3;
    int t = threadIdx.x;
    __shared__ float4 sX[QC][16];
    __shared__ float4 sB4[QC][4];
    __shared__ float4 sSin[HDIMX][4];
    __shared__ float sCum[QC];
    __shared__ float sDt[QC];
    size_t rowbase = (size_t)(b * TT + c * QC);
    int cbase = bh * TT + c * QC;

#pragma unroll
    for (int j = 0; j < 16; j++) {
        int li = t + j * 128;
        int r = li >> 4, p4 = li & 15;
        sX[r][p4] = *(const float4*)(g_CONVX + (rowbase + r) * CONVD + h * 64 + p4 * 4);
    }
#pragma unroll
    for (int j = 0; j < 4; j++) {
        int li = t + j * 128;
        int r = li >> 2, n4 = li & 3;
        sB4[r][n4] = *(const float4*)(g_CONVX + (rowbase + r) * CONVD + 256 + n4 * 4);
    }
    {
        size_t sbase = (size_t)bh * NCHK * (HDIMX * NSTATEX);
        int i0 = t * 8;
        float4 s0 = make_float4(0.f,0.f,0.f,0.f), s1 = s0;
        for (int j = 0; j < c; j++) {
            float dj = __expf(g_CUM[bh * TT + j * QC + QC - 1]);
            float4 a0 = *(const float4*)(g_SLOC + sbase + j * (HDIMX*NSTATEX) + i0);
            float4 a1 = *(const float4*)(g_SLOC + sbase + j * (HDIMX*NSTATEX) + i0 + 4);
            s0.x = s0.x*dj + a0.x; s0.y = s0.y*dj + a0.y;
            s0.z = s0.z*dj + a0.z; s0.w = s0.w*dj + a0.w;
            s1.x = s1.x*dj + a1.x; s1.y = s1.y*dj + a1.y;
            s1.z = s1.z*dj + a1.z; s1.w = s1.w*dj + a1.w;
        }
        sSin[t >> 1][(t & 1) * 2]     = s0;
        sSin[t >> 1][(t & 1) * 2 + 1] = s1;
    }
    sCum[t] = g_CUM[cbase + t];
    sDt[t]  = g_DT[cbase + t];
    float4 c4[4];
#pragma unroll
    for (int n4 = 0; n4 < 4; n4++)
        c4[n4] = *(const float4*)(g_CONVX + (rowbase + t) * CONVD + 272 + n4 * 4);
    __syncthreads();

    float ct  = sCum[t];
    float ect = __expf(ct);
    float Dh  = Dp[h];
    float4 y4[16];
#pragma unroll
    for (int p4 = 0; p4 < 16; p4++) {
        float a0 = 0.f, a1 = 0.f, a2 = 0.f, a3 = 0.f;
#pragma unroll
        for (int n4 = 0; n4 < 4; n4++) {
            float4 cc = c4[n4];
            float4 s0 = sSin[p4*4+0][n4], s1 = sSin[p4*4+1][n4];
            float4 s2 = sSin[p4*4+2][n4], s3 = sSin[p4*4+3][n4];
            a0 += cc.x*s0.x + cc.y*s0.y + cc.z*s0.z + cc.w*s0.w;
            a1 += cc.x*s1.x + cc.y*s1.y + cc.z*s1.z + cc.w*s1.w;
            a2 += cc.x*s2.x + cc.y*s2.y + cc.z*s2.z + cc.w*s2.w;
            a3 += cc.x*s3.x + cc.y*s3.y + cc.z*s3.z + cc.w*s3.w;
        }
        float4 xv = sX[t][p4];
        y4[p4].x = ect * a0 + Dh * xv.x;
        y4[p4].y = ect * a1 + Dh * xv.y;
        y4[p4].z = ect * a2 + Dh * xv.z;
        y4[p4].w = ect * a3 + Dh * xv.w;
    }

    int smax = t | 31;
    for (int s = 0; s <= smax; s++) {
        if (s <= t) {
            float d = 0.f;
#pragma unroll
            for (int n4 = 0; n4 < 4; n4++) {
                float4 cc = c4[n4], bb = sB4[s][n4];
                d += cc.x*bb.x + cc.y*bb.y + cc.z*bb.z + cc.w*bb.w;
            }
            float g = __expf(ct - sCum[s]) * sDt[s] * d;
#pragma unroll
            for (int p4 = 0; p4 < 16; p4++) {
                float4 xv = sX[s][p4];
                y4[p4].x += g * xv.x; y4[p4].y += g * xv.y;
                y4[p4].z += g * xv.z; y4[p4].w += g * xv.w;
            }
        }
    }

    __syncthreads();
#pragma unroll
    for (int p4 = 0; p4 < 16; p4++) sX[t][p4] = y4[p4];
    __syncthreads();
#pragma unroll
    for (int j = 0; j < 16; j++) {
        int li = t + j * 128;
        int r = li >> 4, p4 = li & 15;
        *(float4*)(g_Y + (rowbase + r) * DINNERX + h * 64 + p4 * 4) = sX[r][p4];
    }
}

// --------------------------- gated rmsnorm (float4) --------------------------
__global__ void gatednorm_kernel(const float* __restrict__ gnw)
{
    int warp = (blockIdx.x * blockDim.x + threadIdx.x) >> 5;
    int lane = threadIdx.x & 31;
    if (warp >= BT) return;
    const float4* yr = (const float4*)(g_Y + (size_t)warp * DINNERX);
    const float4* gr = (const float4*)(g_PROJ + (size_t)warp * PROJD);
    float v[8];
    float ss = 0.f;
#pragma unroll
    for (int q = 0; q < 2; q++) {
        float4 yv = yr[lane * 2 + q];
        float4 gv = gr[lane * 2 + q];
        float* vv = v + q * 4;
        float gy[4] = { gv.x, gv.y, gv.z, gv.w };
        float yy[4] = { yv.x, yv.y, yv.z, yv.w };
#pragma unroll
        for (int i = 0; i < 4; i++) {
            float s = gy[i] / (1.f + __expf(-gy[i]));
            float t = yy[i] * s;
            vv[i] = t;
            ss += t * t;
        }
    }
#pragma unroll
    for (int o = 16; o; o >>= 1) ss += __shfl_xor_sync(0xffffffffu, ss, o);
    float r = rsqrtf(ss * (1.f / DINNERX) + EPSF);
    size_t base = (size_t)warp * DINNERX + lane * 8;
    __half h[8];
#pragma unroll
    for (int i = 0; i < 8; i++) h[i] = __float2half_rn(v[i] * r * gnw[lane * 8 + i]);
    *(uint4*)(g_ynh + base) = *(uint4*)h;
}

// ---------------------------- final pool + head ------------------------------
__global__ __launch_bounds__(128) void pool_kernel(const float* __restrict__ nfw)
{
    int b = blockIdx.y;
    int chunk = blockIdx.x;
    int d = threadIdx.x;
    __shared__ float wsum[4];
    float wnf = nfw[d];
    float acc = 0.f;
    for (int r = 0; r < 64; r++) {
        int t = chunk * 64 + r;
        float v = g_H[(size_t)(b * TT + t) * DMX + d];
        float ss = v * v;
#pragma unroll
        for (int o = 16; o; o >>= 1) ss += __shfl_xor_sync(0xffffffffu, ss, o);
        if ((d & 31) == 0) wsum[d >> 5] = ss;
        __syncthreads();
        float tot = wsum[0] + wsum[1] + wsum[2] + wsum[3];
        __syncthreads();
        acc += v * rsqrtf(tot * (1.f / DMX) + EPSF) * wnf;
    }
    g_POOLP[(size_t)(b * 32 + chunk) * DMX + d] = acc * (1.f / TT);
}

__global__ void final_kernel(const float* __restrict__ ow,
                             const float* __restrict__ ob,
                             float* __restrict__ out)
{
    int b = blockIdx.x;
    int j = threadIdx.x;
    __shared__ float p[DMX];
    if (j < DMX) {
        float s = 0.f;
#pragma unroll 8
        for (int k = 0; k < 32; k++) s += g_POOLP[(size_t)(b * 32 + k) * DMX + j];
        p[j] = s;
    }
    __syncthreads();
    float acc = ob[j];
#pragma unroll 4
    for (int k = 0; k < DMX; k++) acc += p[k] * ow[k * DIMX + j];
    out[b * DIMX + j] = acc;
}

// ------------------------------ launcher -------------------------------------
extern "C" void kernel_launch(void* const* d_in, const int* in_sizes, int n_in,
                              void* d_out, int out_size)
{
    const float* x         = (const float*)d_in[0];
    const float* in_w      = (const float*)d_in[1];
    const float* in_b      = (const float*)d_in[2];
    const float* norm_w    = (const float*)d_in[3];
    const float* inproj_w  = (const float*)d_in[4];
    const float* conv_w    = (const float*)d_in[5];
    const float* conv_b    = (const float*)d_in[6];
    const float* A_log     = (const float*)d_in[7];
    const float* Dparam    = (const float*)d_in[8];
    const float* dt_bias   = (const float*)d_in[9];
    const float* gnorm_w   = (const float*)d_in[10];
    const float* outproj_w = (const float*)d_in[11];
    const float* normf_w   = (const float*)d_in[12];
    const float* out_w     = (const float*)d_in[13];
    const float* out_b     = (const float*)d_in[14];

    float *pH, *pPROJ;
    __half *pXh, *pHNh, *pYNh;
    __half *pW1hi, *pW1lo, *pW2hi, *pW2lo, *pW3hi, *pW3lo;
    cudaGetSymbolAddress((void**)&pH,    g_H);
    cudaGetSymbolAddress((void**)&pPROJ, g_PROJ);
    cudaGetSymbolAddress((void**)&pXh,   g_xh);
    cudaGetSymbolAddress((void**)&pHNh,  g_hnh);
    cudaGetSymbolAddress((void**)&pYNh,  g_ynh);
    cudaGetSymbolAddress((void**)&pW1hi, g_w1hi);
    cudaGetSymbolAddress((void**)&pW1lo, g_w1lo);
    cudaGetSymbolAddress((void**)&pW2hi, g_w2hi);
    cudaGetSymbolAddress((void**)&pW2lo, g_w2lo);
    cudaGetSymbolAddress((void**)&pW3hi, g_w3hi);
    cudaGetSymbolAddress((void**)&pW3lo, g_w3lo);

    cudaFuncSetAttribute(mma_gemm<0>, cudaFuncAttributeMaxDynamicSharedMemorySize, SM_TOTAL);
    cudaFuncSetAttribute(mma_gemm<1>, cudaFuncAttributeMaxDynamicSharedMemorySize, SM_TOTAL);
    cudaFuncSetAttribute(mma_gemm<2>, cudaFuncAttributeMaxDynamicSharedMemorySize, SM_TOTAL);

    // 0: x -> fp16
    split_kernel<<<(BT * DIMX / 4 + 255) / 256, 256>>>(x, pXh, BT * DIMX / 4);
    // 1: all weight transposes+splits
    tsplit_all<<<(TS_R1 + TS_R2 + TS_R3 + 255) / 256, 256>>>(in_w, inproj_w, outproj_w);
    // 2: h = x @ in_w + in_b
    mma_gemm<0><<<dim3(DMX / 64, BT / 128), 256, SM_TOTAL>>>(
        pXh, pW1hi, pW1lo, in_b, pH, DMX, DIMX);

    for (int l = 0; l < LNUM; l++) {
        rmsnorm128_kernel<<<BT / 8, 256>>>(pH, norm_w + l * DMX, pHNh);
        mma_gemm<1><<<dim3(PROJPAD / 64, BT / 128), 256, SM_TOTAL>>>(
            pHNh,
            pW2hi + (size_t)l * PROJPAD * DMX, pW2lo + (size_t)l * PROJPAD * DMX,
            nullptr, pPROJ, PROJD, DMX);
        conv_kernel<<<dim3(TT / 64, BB), 288>>>(
            conv_w + l * CONVD * 4, conv_b + l * CONVD);
        chunkstate_kernel<<<dim3(NCHK, BHX), 256>>>(A_log + l * NHX, dt_bias + l * NHX);
        ssd_out_kernel<<<dim3(NCHK, BHX), QC>>>(Dparam + l * NHX);
        gatednorm_kernel<<<BT / 8, 256>>>(gnorm_w + l * DINNERX);
        mma_gemm<2><<<dim3(DMX / 64, BT / 128), 256, SM_TOTAL>>>(
            pYNh,
            pW3hi + (size_t)l * DMX * DINNERX, pW3lo + (size_t)l * DMX * DINNERX,
            nullptr, pH, DMX, DINNERX);
    }

    pool_kernel<<<dim3(32, BB), DMX>>>(normf_w);
    final_kernel<<<BB, DIMX>>>(out_w, out_b, (float*)d_out);
}